// round 8
// baseline (speedup 1.0000x reference)
#include <cuda_runtime.h>
#include <math.h>
#include <stdint.h>

#define N_NODES 50000
#define N_EDGES 600000
#define IN_DIM  384
#define HID     128
#define HYP     256
#define EPSV    1e-10f
#define LATB    143
#define NPB     352          // 143*352 = 50336 >= 50000

// ---------------- scratch ----------------
__device__ float g_xemb[N_NODES * HID];
__device__ float g_acc [N_NODES * HID];
__device__ float g_curA[N_NODES * HID];
__device__ float g_curB[N_NODES * HID];
__device__ float g_Hm  [N_NODES * HYP];
__device__ float g_lat [HYP * HID];
__device__ float g_latP[LATB * HYP * HID];
__device__ float g_dinv[N_NODES];
__device__ int2  g_csr2[N_EDGES];
__device__ int   g_deg [N_NODES];
__device__ int   g_rowptr[N_NODES + 1];
__device__ int   g_fill[N_NODES];
__device__ int   g_part[64];

// ---------------- tf32 mma helpers ----------------
__device__ __forceinline__ uint32_t tf32c(float f) {
    uint32_t r;
    asm("cvt.rna.tf32.f32 %0, %1;" : "=r"(r) : "f"(f));
    return r;
}

__device__ __forceinline__ uint4 tf32c4(float4 v) {
    uint4 r;
    r.x = tf32c(v.x); r.y = tf32c(v.y); r.z = tf32c(v.z); r.w = tf32c(v.w);
    return r;
}

__device__ __forceinline__ void mma8(float* c,
                                     uint32_t a0, uint32_t a1, uint32_t a2, uint32_t a3,
                                     uint32_t b0, uint32_t b1) {
    asm volatile(
        "mma.sync.aligned.m16n8k8.row.col.f32.tf32.tf32.f32 "
        "{%0,%1,%2,%3},{%4,%5,%6,%7},{%8,%9},{%0,%1,%2,%3};"
        : "+f"(c[0]), "+f"(c[1]), "+f"(c[2]), "+f"(c[3])
        : "r"(a0), "r"(a1), "r"(a2), "r"(a3), "r"(b0), "r"(b1));
}

// ---------------- setup kernels ----------------
__global__ void k_zero() {
    int i = blockIdx.x * blockDim.x + threadIdx.x;
    if (i < N_NODES) { g_deg[i] = 0; g_fill[i] = 0; }
}

__global__ void k_deg(const int* __restrict__ dst) {
    int e = blockIdx.x * blockDim.x + threadIdx.x;
    if (e < N_EDGES) atomicAdd(&g_deg[dst[e]], 1);
}

__global__ void k_scan1() {
    __shared__ int sh[1024];
    int i = blockIdx.x * 1024 + threadIdx.x;
    int v = (i < N_NODES) ? g_deg[i] : 0;
    sh[threadIdx.x] = v;
    __syncthreads();
    for (int off = 1; off < 1024; off <<= 1) {
        int t = (threadIdx.x >= off) ? sh[threadIdx.x - off] : 0;
        __syncthreads();
        sh[threadIdx.x] += t;
        __syncthreads();
    }
    if (i < N_NODES) g_rowptr[i] = sh[threadIdx.x] - v;
    if (threadIdx.x == 1023) g_part[blockIdx.x] = sh[1023];
}

__global__ void k_scan2(int nb) {
    __shared__ int sh[64];
    int v = (threadIdx.x < nb) ? g_part[threadIdx.x] : 0;
    sh[threadIdx.x] = v;
    __syncthreads();
    for (int off = 1; off < 64; off <<= 1) {
        int t = (threadIdx.x >= off) ? sh[threadIdx.x - off] : 0;
        __syncthreads();
        sh[threadIdx.x] += t;
        __syncthreads();
    }
    if (threadIdx.x < nb) g_part[threadIdx.x] = sh[threadIdx.x] - v;
}

__global__ void k_scan3() {
    int i = blockIdx.x * 1024 + threadIdx.x;
    if (i < N_NODES) g_rowptr[i] += g_part[blockIdx.x];
}

__global__ void k_dinv() {
    int i = blockIdx.x * blockDim.x + threadIdx.x;
    if (i == 0) g_rowptr[N_NODES] = N_EDGES;
    if (i < N_NODES) {
        int d = g_deg[i];
        g_dinv[i] = (d > 0) ? rsqrtf((float)d) : 0.f;
    }
}

__global__ void k_fill(const int* __restrict__ src, const int* __restrict__ dst) {
    int e = blockIdx.x * blockDim.x + threadIdx.x;
    if (e < N_EDGES) {
        int d = dst[e], s = src[e];
        int pos = g_rowptr[d] + atomicAdd(&g_fill[d], 1);
        g_csr2[pos] = make_int2(s, __float_as_int(g_dinv[s] * g_dinv[d]));
    }
}

// ---------------- G1: x_emb = x @ w_feat + b_feat ; acc = x_emb ----------------
// Register-pipelined: next chunk LDG issued before MMA of current chunk.
__global__ __launch_bounds__(256) void k_gemm1(const float* __restrict__ x,
                                               const float* __restrict__ w,
                                               const float* __restrict__ b) {
    __shared__ uint32_t As[128 * 20];
    __shared__ uint32_t Bs[16 * 136];
    int t = threadIdx.x, lane = t & 31, wid = t >> 5;
    int g = lane >> 2, t4 = lane & 3;
    int r0 = blockIdx.x * 128, m0 = wid * 16;
    float acc[16][4];
#pragma unroll
    for (int n = 0; n < 16; n++) { acc[n][0] = acc[n][1] = acc[n][2] = acc[n][3] = 0.f; }

    int arow = t >> 2, ac = (t & 3) * 4;
    int ga0 = min(r0 + arow, N_NODES - 1), ga1 = min(r0 + arow + 64, N_NODES - 1);
    int brow = t >> 5, bc = (t & 31) * 4;

    float4 ra0 = *(const float4*)(x + (size_t)ga0 * IN_DIM + ac);
    float4 ra1 = *(const float4*)(x + (size_t)ga1 * IN_DIM + ac);
    float4 rb0 = *(const float4*)(w + brow * HID + bc);
    float4 rb1 = *(const float4*)(w + (brow + 8) * HID + bc);

    for (int c = 0; c < IN_DIM / 16; c++) {
        *(uint4*)&As[arow * 20 + ac]        = tf32c4(ra0);
        *(uint4*)&As[(arow + 64) * 20 + ac] = tf32c4(ra1);
        *(uint4*)&Bs[brow * 136 + bc]       = tf32c4(rb0);
        *(uint4*)&Bs[(brow + 8) * 136 + bc] = tf32c4(rb1);
        __syncthreads();
        if (c + 1 < IN_DIM / 16) {
            int k0 = (c + 1) * 16;
            ra0 = *(const float4*)(x + (size_t)ga0 * IN_DIM + k0 + ac);
            ra1 = *(const float4*)(x + (size_t)ga1 * IN_DIM + k0 + ac);
            rb0 = *(const float4*)(w + (k0 + brow) * HID + bc);
            rb1 = *(const float4*)(w + (k0 + brow + 8) * HID + bc);
        }
#pragma unroll
        for (int ks = 0; ks < 2; ks++) {
            int ar = (m0 + g) * 20 + ks * 8 + t4;
            uint32_t a0 = As[ar], a1 = As[ar + 160], a2 = As[ar + 4], a3 = As[ar + 164];
            const uint32_t* bp = &Bs[(ks * 8 + t4) * 136];
#pragma unroll
            for (int nt = 0; nt < 16; nt++)
                mma8(acc[nt], a0, a1, a2, a3, bp[nt * 8 + g], bp[544 + nt * 8 + g]);
        }
        __syncthreads();
    }
    int rA = r0 + m0 + g, rB = rA + 8;
#pragma unroll
    for (int nt = 0; nt < 16; nt++) {
        int cn = nt * 8 + t4 * 2;
        float b0 = b[cn], b1 = b[cn + 1];
        if (rA < N_NODES) {
            float2 v = make_float2(acc[nt][0] + b0, acc[nt][1] + b1);
            *(float2*)&g_xemb[rA * HID + cn] = v;
            *(float2*)&g_acc [rA * HID + cn] = v;
        }
        if (rB < N_NODES) {
            float2 v = make_float2(acc[nt][2] + b0, acc[nt][3] + b1);
            *(float2*)&g_xemb[rB * HID + cn] = v;
            *(float2*)&g_acc [rB * HID + cn] = v;
        }
    }
}

// ---------------- propagation: warp per node, float4 ----------------
__global__ __launch_bounds__(128) void k_prop(int step) {
    const float* cur = (step == 0) ? g_xemb : ((step == 1) ? g_curA : g_curB);
    float*       nxt = (step == 0) ? g_curA : ((step == 1) ? g_curB : g_curA);
    int d = blockIdx.x * 4 + (threadIdx.x >> 5);
    if (d >= N_NODES) return;
    int lane = threadIdx.x & 31;
    int s0 = g_rowptr[d], s1 = g_rowptr[d + 1];
    float4 sum = make_float4(0.f, 0.f, 0.f, 0.f);
    for (int j = s0; j < s1; j++) {
        int2 e = g_csr2[j];
        float v = __int_as_float(e.y);
        float4 c4v = *(const float4*)&cur[(size_t)e.x * HID + lane * 4];
        sum.x = fmaf(c4v.x, v, sum.x);
        sum.y = fmaf(c4v.y, v, sum.y);
        sum.z = fmaf(c4v.z, v, sum.z);
        sum.w = fmaf(c4v.w, v, sum.w);
    }
    size_t o = (size_t)d * HID + lane * 4;
    *(float4*)&nxt[o] = sum;
    float4 a = *(const float4*)&g_acc[o];
    a.x += sum.x; a.y += sum.y; a.z += sum.z; a.w += sum.w;
    *(float4*)&g_acc[o] = a;
}

// ---------------- Hm = softmax((x_emb @ w_hyper + gumbel)*2) ----------------
__global__ __launch_bounds__(256) void k_hyp(const float* __restrict__ wh,
                                             const float* __restrict__ u) {
    __shared__ uint32_t As[128 * 20];
    __shared__ uint32_t Bs[16 * 264];
    int t = threadIdx.x, lane = t & 31, wid = t >> 5;
    int g = lane >> 2, t4 = lane & 3;
    int r0 = blockIdx.x * 128, m0 = wid * 16;
    float acc[32][4];
#pragma unroll
    for (int n = 0; n < 32; n++) { acc[n][0] = acc[n][1] = acc[n][2] = acc[n][3] = 0.f; }

    int arow = t >> 2, ac = (t & 3) * 4;
    int ga0 = min(r0 + arow, N_NODES - 1), ga1 = min(r0 + arow + 64, N_NODES - 1);
    int brow = t >> 6, bc = (t & 63) * 4;

    float4 ra0 = *(const float4*)(g_xemb + (size_t)ga0 * HID + ac);
    float4 ra1 = *(const float4*)(g_xemb + (size_t)ga1 * HID + ac);
    float4 rb[4];
#pragma unroll
    for (int l = 0; l < 4; l++)
        rb[l] = *(const float4*)(wh + (brow + l * 4) * HYP + bc);

    for (int c = 0; c < HID / 16; c++) {
        *(uint4*)&As[arow * 20 + ac]        = tf32c4(ra0);
        *(uint4*)&As[(arow + 64) * 20 + ac] = tf32c4(ra1);
#pragma unroll
        for (int l = 0; l < 4; l++)
            *(uint4*)&Bs[(brow + l * 4) * 264 + bc] = tf32c4(rb[l]);
        __syncthreads();
        if (c + 1 < HID / 16) {
            int k0 = (c + 1) * 16;
            ra0 = *(const float4*)(g_xemb + (size_t)ga0 * HID + k0 + ac);
            ra1 = *(const float4*)(g_xemb + (size_t)ga1 * HID + k0 + ac);
#pragma unroll
            for (int l = 0; l < 4; l++)
                rb[l] = *(const float4*)(wh + (k0 + brow + l * 4) * HYP + bc);
        }
#pragma unroll
        for (int ks = 0; ks < 2; ks++) {
            int ar = (m0 + g) * 20 + ks * 8 + t4;
            uint32_t a0 = As[ar], a1 = As[ar + 160], a2 = As[ar + 4], a3 = As[ar + 164];
            const uint32_t* bp = &Bs[(ks * 8 + t4) * 264];
#pragma unroll
            for (int nt = 0; nt < 32; nt++)
                mma8(acc[nt], a0, a1, a2, a3, bp[nt * 8 + g], bp[1056 + nt * 8 + g]);
        }
        __syncthreads();
    }

    int rA = r0 + m0 + g, rB = rA + 8;
    int uA = min(rA, N_NODES - 1), uB = min(rB, N_NODES - 1);
    float mA = -1e30f, mB = -1e30f;
#pragma unroll
    for (int nt = 0; nt < 32; nt++) {
        int cn = nt * 8 + t4 * 2;
        float2 ua = *(const float2*)(u + (size_t)uA * HYP + cn);
        float2 ub = *(const float2*)(u + (size_t)uB * HYP + cn);
        acc[nt][0] = (acc[nt][0] - __logf(-logf(ua.x + EPSV) + EPSV)) * 2.f;
        acc[nt][1] = (acc[nt][1] - __logf(-logf(ua.y + EPSV) + EPSV)) * 2.f;
        acc[nt][2] = (acc[nt][2] - __logf(-logf(ub.x + EPSV) + EPSV)) * 2.f;
        acc[nt][3] = (acc[nt][3] - __logf(-logf(ub.y + EPSV) + EPSV)) * 2.f;
        mA = fmaxf(mA, fmaxf(acc[nt][0], acc[nt][1]));
        mB = fmaxf(mB, fmaxf(acc[nt][2], acc[nt][3]));
    }
    mA = fmaxf(mA, __shfl_xor_sync(0xffffffffu, mA, 1));
    mA = fmaxf(mA, __shfl_xor_sync(0xffffffffu, mA, 2));
    mB = fmaxf(mB, __shfl_xor_sync(0xffffffffu, mB, 1));
    mB = fmaxf(mB, __shfl_xor_sync(0xffffffffu, mB, 2));
    float sA = 0.f, sB = 0.f;
#pragma unroll
    for (int nt = 0; nt < 32; nt++) {
        acc[nt][0] = __expf(acc[nt][0] - mA);
        acc[nt][1] = __expf(acc[nt][1] - mA);
        acc[nt][2] = __expf(acc[nt][2] - mB);
        acc[nt][3] = __expf(acc[nt][3] - mB);
        sA += acc[nt][0] + acc[nt][1];
        sB += acc[nt][2] + acc[nt][3];
    }
    sA += __shfl_xor_sync(0xffffffffu, sA, 1);
    sA += __shfl_xor_sync(0xffffffffu, sA, 2);
    sB += __shfl_xor_sync(0xffffffffu, sB, 1);
    sB += __shfl_xor_sync(0xffffffffu, sB, 2);
    float iA = 1.f / sA, iB = 1.f / sB;
#pragma unroll
    for (int nt = 0; nt < 32; nt++) {
        int cn = nt * 8 + t4 * 2;
        if (rA < N_NODES)
            *(float2*)&g_Hm[(size_t)rA * HYP + cn] = make_float2(acc[nt][0] * iA, acc[nt][1] * iA);
        if (rB < N_NODES)
            *(float2*)&g_Hm[(size_t)rB * HYP + cn] = make_float2(acc[nt][2] * iB, acc[nt][3] * iB);
    }
}

// ---------------- lat partials: latP[b] = Hm[rows_b]^T @ xemb[rows_b] ----------------
__global__ __launch_bounds__(512) void k_lat() {
    __shared__ uint32_t Hs[16 * 264];
    __shared__ uint32_t Xs[16 * 136];
    int t = threadIdx.x, lane = t & 31, wid = t >> 5;
    int g = lane >> 2, t4 = lane & 3;
    int h0 = wid * 16;
    int base = blockIdx.x * NPB;
    float acc[16][4];
#pragma unroll
    for (int n = 0; n < 16; n++) { acc[n][0] = acc[n][1] = acc[n][2] = acc[n][3] = 0.f; }

    int hrow = t >> 6, hc = (t & 63) * 4;     // rows 0..7, +8
    int xrow = t >> 5, xc = (t & 31) * 4;     // rows 0..15

    float4 rh0, rh1, rx;
    {
        int n0 = base + hrow, n1 = base + hrow + 8, n2 = base + xrow;
        rh0 = (n0 < N_NODES) ? *(const float4*)&g_Hm[(size_t)n0 * HYP + hc] : make_float4(0,0,0,0);
        rh1 = (n1 < N_NODES) ? *(const float4*)&g_Hm[(size_t)n1 * HYP + hc] : make_float4(0,0,0,0);
        rx  = (n2 < N_NODES) ? *(const float4*)&g_xemb[(size_t)n2 * HID + xc] : make_float4(0,0,0,0);
    }

    for (int c = 0; c < NPB; c += 16) {
        *(uint4*)&Hs[hrow * 264 + hc]       = tf32c4(rh0);
        *(uint4*)&Hs[(hrow + 8) * 264 + hc] = tf32c4(rh1);
        *(uint4*)&Xs[xrow * 136 + xc]       = tf32c4(rx);
        __syncthreads();
        if (c + 16 < NPB) {
            int n0 = base + c + 16 + hrow, n1 = n0 + 8, n2 = base + c + 16 + xrow;
            rh0 = (n0 < N_NODES) ? *(const float4*)&g_Hm[(size_t)n0 * HYP + hc] : make_float4(0,0,0,0);
            rh1 = (n1 < N_NODES) ? *(const float4*)&g_Hm[(size_t)n1 * HYP + hc] : make_float4(0,0,0,0);
            rx  = (n2 < N_NODES) ? *(const float4*)&g_xemb[(size_t)n2 * HID + xc] : make_float4(0,0,0,0);
        }
#pragma unroll
        for (int ks = 0; ks < 2; ks++) {
            const uint32_t* hp  = &Hs[(ks * 8 + t4) * 264];
            const uint32_t* hp4 = hp + 4 * 264;
            uint32_t a0 = hp[h0 + g],  a1 = hp[h0 + g + 8];
            uint32_t a2 = hp4[h0 + g], a3 = hp4[h0 + g + 8];
            const uint32_t* bp = &Xs[(ks * 8 + t4) * 136];
#pragma unroll
            for (int nt = 0; nt < 16; nt++)
                mma8(acc[nt], a0, a1, a2, a3, bp[nt * 8 + g], bp[544 + nt * 8 + g]);
        }
        __syncthreads();
    }
    float* pb = &g_latP[(size_t)blockIdx.x * HYP * HID];
#pragma unroll
    for (int nt = 0; nt < 16; nt++) {
        int cn = nt * 8 + t4 * 2;
        *(float2*)&pb[(h0 + g) * HID + cn]     = make_float2(acc[nt][0], acc[nt][1]);
        *(float2*)&pb[(h0 + g + 8) * HID + cn] = make_float2(acc[nt][2], acc[nt][3]);
    }
}

__global__ void k_latred() {
    int i = blockIdx.x * blockDim.x + threadIdx.x;
    if (i < HYP * HID) {
        float s = 0.f;
        for (int b = 0; b < LATB; b++) s += g_latP[(size_t)b * HYP * HID + i];
        g_lat[i] = s;
    }
}

// ------- fused: final = acc/4 + 0.1*normalize(Hm@lat); vis/txt = relu(final@W+b) -------
__global__ __launch_bounds__(256) void k_finalout(float* __restrict__ outF,
                                                  const float* __restrict__ wv, const float* __restrict__ bv,
                                                  const float* __restrict__ wt, const float* __restrict__ bt,
                                                  float* __restrict__ vis, float* __restrict__ txt) {
    __shared__ uint32_t As[128 * 20];
    __shared__ uint32_t Bs[16 * 136];
    int t = threadIdx.x, lane = t & 31, wid = t >> 5;
    int g = lane >> 2, t4 = lane & 3;
    int r0 = blockIdx.x * 128, m0 = wid * 16;
    float acc[16][4];
#pragma unroll
    for (int n = 0; n < 16; n++) { acc[n][0] = acc[n][1] = acc[n][2] = acc[n][3] = 0.f; }

    int arow = t >> 2, ac = (t & 3) * 4;
    int ga0 = min(r0 + arow, N_NODES - 1), ga1 = min(r0 + arow + 64, N_NODES - 1);
    int brow = t >> 5, bc = (t & 31) * 4;

    // ---- phase 1: hyper_out = Hm @ lat ----
    float4 ra0 = *(const float4*)(g_Hm + (size_t)ga0 * HYP + ac);
    float4 ra1 = *(const float4*)(g_Hm + (size_t)ga1 * HYP + ac);
    float4 rb0 = *(const float4*)(g_lat + brow * HID + bc);
    float4 rb1 = *(const float4*)(g_lat + (brow + 8) * HID + bc);

    for (int c = 0; c < HYP / 16; c++) {
        *(uint4*)&As[arow * 20 + ac]        = tf32c4(ra0);
        *(uint4*)&As[(arow + 64) * 20 + ac] = tf32c4(ra1);
        *(uint4*)&Bs[brow * 136 + bc]       = tf32c4(rb0);
        *(uint4*)&Bs[(brow + 8) * 136 + bc] = tf32c4(rb1);
        __syncthreads();
        if (c + 1 < HYP / 16) {
            int k0 = (c + 1) * 16;
            ra0 = *(const float4*)(g_Hm + (size_t)ga0 * HYP + k0 + ac);
            ra1 = *(const float4*)(g_Hm + (size_t)ga1 * HYP + k0 + ac);
            rb0 = *(const float4*)(g_lat + (k0 + brow) * HID + bc);
            rb1 = *(const float4*)(g_lat + (k0 + brow + 8) * HID + bc);
        }
#pragma unroll
        for (int ks = 0; ks < 2; ks++) {
            int ar = (m0 + g) * 20 + ks * 8 + t4;
            uint32_t a0 = As[ar], a1 = As[ar + 160], a2 = As[ar + 4], a3 = As[ar + 164];
            const uint32_t* bp = &Bs[(ks * 8 + t4) * 136];
#pragma unroll
            for (int nt = 0; nt < 16; nt++)
                mma8(acc[nt], a0, a1, a2, a3, bp[nt * 8 + g], bp[544 + nt * 8 + g]);
        }
        __syncthreads();
    }

    // ---- epilogue: normalize + blend; keep final in acc ----
    float ssA = 0.f, ssB = 0.f;
#pragma unroll
    for (int nt = 0; nt < 16; nt++) {
        ssA += acc[nt][0] * acc[nt][0] + acc[nt][1] * acc[nt][1];
        ssB += acc[nt][2] * acc[nt][2] + acc[nt][3] * acc[nt][3];
    }
    ssA += __shfl_xor_sync(0xffffffffu, ssA, 1);
    ssA += __shfl_xor_sync(0xffffffffu, ssA, 2);
    ssB += __shfl_xor_sync(0xffffffffu, ssB, 1);
    ssB += __shfl_xor_sync(0xffffffffu, ssB, 2);
    float iA = 0.1f / fmaxf(sqrtf(ssA), 1e-12f);
    float iB = 0.1f / fmaxf(sqrtf(ssB), 1e-12f);
    int rA = r0 + m0 + g, rB = rA + 8;
    int rAc = min(rA, N_NODES - 1), rBc = min(rB, N_NODES - 1);
#pragma unroll
    for (int nt = 0; nt < 16; nt++) {
        int cn = nt * 8 + t4 * 2;
        float2 agA = *(const float2*)&g_acc[rAc * HID + cn];
        float2 agB = *(const float2*)&g_acc[rBc * HID + cn];
        acc[nt][0] = agA.x * 0.25f + acc[nt][0] * iA;
        acc[nt][1] = agA.y * 0.25f + acc[nt][1] * iA;
        acc[nt][2] = agB.x * 0.25f + acc[nt][2] * iB;
        acc[nt][3] = agB.y * 0.25f + acc[nt][3] * iB;
        if (rA < N_NODES)
            *(float2*)&outF[(size_t)rA * HID + cn] = make_float2(acc[nt][0], acc[nt][1]);
        if (rB < N_NODES)
            *(float2*)&outF[(size_t)rB * HID + cn] = make_float2(acc[nt][2], acc[nt][3]);
    }

    // ---- phase 2: vis/txt GEMMs from register-resident final ----
    float accV[16][4];
    for (int p = 0; p < 2; p++) {
        const float* w = p ? wt : wv;
#pragma unroll
        for (int n = 0; n < 16; n++) { accV[n][0] = accV[n][1] = accV[n][2] = accV[n][3] = 0.f; }
        rb0 = *(const float4*)(w + brow * HID + bc);
        rb1 = *(const float4*)(w + (brow + 8) * HID + bc);
#pragma unroll
        for (int c = 0; c < HID / 16; c++) {
            // stage A slice (cols c*16 .. +15 of final) from registers
            const int ntA = c * 2;
            uint2 v;
            v.x = tf32c(acc[ntA][0]);     v.y = tf32c(acc[ntA][1]);
            *(uint2*)&As[(m0 + g) * 20 + t4 * 2] = v;
            v.x = tf32c(acc[ntA][2]);     v.y = tf32c(acc[ntA][3]);
            *(uint2*)&As[(m0 + g + 8) * 20 + t4 * 2] = v;
            v.x = tf32c(acc[ntA + 1][0]); v.y = tf32c(acc[ntA + 1][1]);
            *(uint2*)&As[(m0 + g) * 20 + 8 + t4 * 2] = v;
            v.x = tf32c(acc[ntA + 1][2]); v.y = tf32c(acc[ntA + 1][3]);
            *(uint2*)&As[(m0 + g + 8) * 20 + 8 + t4 * 2] = v;
            *(uint4*)&Bs[brow * 136 + bc]       = tf32c4(rb0);
            *(uint4*)&Bs[(brow + 8) * 136 + bc] = tf32c4(rb1);
            __syncthreads();
            if (c + 1 < HID / 16) {
                int k0 = (c + 1) * 16;
                rb0 = *(const float4*)(w + (k0 + brow) * HID + bc);
                rb1 = *(const float4*)(w + (k0 + brow + 8) * HID + bc);
            }
#pragma unroll
            for (int ks = 0; ks < 2; ks++) {
                int ar = (m0 + g) * 20 + ks * 8 + t4;
                uint32_t a0 = As[ar], a1 = As[ar + 160], a2 = As[ar + 4], a3 = As[ar + 164];
                const uint32_t* bp = &Bs[(ks * 8 + t4) * 136];
#pragma unroll
                for (int nt = 0; nt < 16; nt++)
                    mma8(accV[nt], a0, a1, a2, a3, bp[nt * 8 + g], bp[544 + nt * 8 + g]);
            }
            __syncthreads();
        }
        const float* bias = p ? bt : bv;
        float* o = p ? txt : vis;
#pragma unroll
        for (int nt = 0; nt < 16; nt++) {
            int cn = nt * 8 + t4 * 2;
            float b0 = bias[cn], b1 = bias[cn + 1];
            if (rA < N_NODES)
                *(float2*)&o[(size_t)rA * HID + cn] =
                    make_float2(fmaxf(accV[nt][0] + b0, 0.f), fmaxf(accV[nt][1] + b1, 0.f));
            if (rB < N_NODES)
                *(float2*)&o[(size_t)rB * HID + cn] =
                    make_float2(fmaxf(accV[nt][2] + b0, 0.f), fmaxf(accV[nt][3] + b1, 0.f));
        }
    }
}

// ---------------- launcher ----------------
extern "C" void kernel_launch(void* const* d_in, const int* in_sizes, int n_in,
                              void* d_out, int out_size) {
    const float* x       = (const float*)d_in[0];
    const int*   ei      = (const int*)  d_in[1];
    const float* u       = (const float*)d_in[2];
    const float* w_feat  = (const float*)d_in[3];
    const float* b_feat  = (const float*)d_in[4];
    const float* w_hyper = (const float*)d_in[5];
    const float* w_vis   = (const float*)d_in[6];
    const float* b_vis   = (const float*)d_in[7];
    const float* w_txt   = (const float*)d_in[8];
    const float* b_txt   = (const float*)d_in[9];

    float* out  = (float*)d_out;
    float* outF = out;
    float* outV = out + (size_t)N_NODES * HID;
    float* outT = out + (size_t)2 * N_NODES * HID;

    const int* src = ei;
    const int* dst = ei + N_EDGES;

    int nb = (N_NODES + 1023) / 1024;         // 49
    int g128 = (N_NODES + 127) / 128;         // 391

    k_zero <<<(N_NODES + 255) / 256, 256>>>();
    k_deg  <<<(N_EDGES + 255) / 256, 256>>>(dst);
    k_scan1<<<nb, 1024>>>();
    k_scan2<<<1, 64>>>(nb);
    k_scan3<<<nb, 1024>>>();
    k_dinv <<<(N_NODES + 255) / 256, 256>>>();
    k_fill <<<(N_EDGES + 255) / 256, 256>>>(src, dst);

    k_gemm1<<<g128, 256>>>(x, w_feat, b_feat);

    k_prop<<<(N_NODES + 3) / 4, 128>>>(0);
    k_prop<<<(N_NODES + 3) / 4, 128>>>(1);
    k_prop<<<(N_NODES + 3) / 4, 128>>>(2);

    k_hyp<<<g128, 256>>>(w_hyper, u);

    k_lat<<<LATB, 512>>>();
    k_latred<<<(HYP * HID + 1023) / 1024, 1024>>>();

    k_finalout<<<g128, 256>>>(outF, w_vis, b_vis, w_txt, b_txt, outV, outT);
}

// round 12
// speedup vs baseline: 1.2484x; 1.2484x over previous
#include <cuda_runtime.h>
#include <math.h>
#include <stdint.h>

#define N_NODES 50000
#define N_EDGES 600000
#define IN_DIM  384
#define HID     128
#define HYP     256
#define EPSV    1e-10f
#define LATB    143
#define NPB     352          // 143*352 = 50336 >= 50000

// ---------------- scratch ----------------
__device__ float g_xemb[N_NODES * HID];
__device__ float g_acc [N_NODES * HID];
__device__ float g_curA[N_NODES * HID];
__device__ float g_curB[N_NODES * HID];
__device__ float g_Hm  [N_NODES * HYP];
__device__ float g_lat [HYP * HID];
__device__ float g_latP[LATB * HYP * HID];
__device__ float g_dinv[N_NODES];
__device__ int2  g_csr2[N_EDGES];
__device__ int   g_deg [N_NODES];
__device__ int   g_rowptr[N_NODES + 1];
__device__ int   g_fill[N_NODES];
__device__ int   g_part[64];

// ---------------- tf32 mma helpers ----------------
__device__ __forceinline__ uint32_t tf32c(float f) {
    uint32_t r;
    asm("cvt.rna.tf32.f32 %0, %1;" : "=r"(r) : "f"(f));
    return r;
}

__device__ __forceinline__ uint4 tf32c4(float4 v) {
    uint4 r;
    r.x = tf32c(v.x); r.y = tf32c(v.y); r.z = tf32c(v.z); r.w = tf32c(v.w);
    return r;
}

__device__ __forceinline__ void mma8(float* c,
                                     uint32_t a0, uint32_t a1, uint32_t a2, uint32_t a3,
                                     uint32_t b0, uint32_t b1) {
    asm volatile(
        "mma.sync.aligned.m16n8k8.row.col.f32.tf32.tf32.f32 "
        "{%0,%1,%2,%3},{%4,%5,%6,%7},{%8,%9},{%0,%1,%2,%3};"
        : "+f"(c[0]), "+f"(c[1]), "+f"(c[2]), "+f"(c[3])
        : "r"(a0), "r"(a1), "r"(a2), "r"(a3), "r"(b0), "r"(b1));
}

// ---------------- setup kernels ----------------
__global__ void k_zero() {
    int i = blockIdx.x * blockDim.x + threadIdx.x;
    if (i < N_NODES) { g_deg[i] = 0; g_fill[i] = 0; }
}

__global__ void k_deg(const int* __restrict__ dst) {
    int e = blockIdx.x * blockDim.x + threadIdx.x;
    if (e < N_EDGES) atomicAdd(&g_deg[dst[e]], 1);
}

__global__ void k_scan1() {
    __shared__ int sh[1024];
    int i = blockIdx.x * 1024 + threadIdx.x;
    int v = (i < N_NODES) ? g_deg[i] : 0;
    sh[threadIdx.x] = v;
    __syncthreads();
    for (int off = 1; off < 1024; off <<= 1) {
        int t = (threadIdx.x >= off) ? sh[threadIdx.x - off] : 0;
        __syncthreads();
        sh[threadIdx.x] += t;
        __syncthreads();
    }
    if (i < N_NODES) g_rowptr[i] = sh[threadIdx.x] - v;
    if (threadIdx.x == 1023) g_part[blockIdx.x] = sh[1023];
}

__global__ void k_scan2(int nb) {
    __shared__ int sh[64];
    int v = (threadIdx.x < nb) ? g_part[threadIdx.x] : 0;
    sh[threadIdx.x] = v;
    __syncthreads();
    for (int off = 1; off < 64; off <<= 1) {
        int t = (threadIdx.x >= off) ? sh[threadIdx.x - off] : 0;
        __syncthreads();
        sh[threadIdx.x] += t;
        __syncthreads();
    }
    if (threadIdx.x < nb) g_part[threadIdx.x] = sh[threadIdx.x] - v;
}

// scan finalize + dinv fused (one fewer launch in the serial chain)
__global__ void k_scan3() {
    int i = blockIdx.x * 1024 + threadIdx.x;
    if (i < N_NODES) {
        g_rowptr[i] += g_part[blockIdx.x];
        int d = g_deg[i];
        g_dinv[i] = (d > 0) ? rsqrtf((float)d) : 0.f;
    }
    if (i == 0) g_rowptr[N_NODES] = N_EDGES;
}

__global__ void k_fill(const int* __restrict__ src, const int* __restrict__ dst) {
    int e = blockIdx.x * blockDim.x + threadIdx.x;
    if (e < N_EDGES) {
        int d = dst[e], s = src[e];
        int pos = g_rowptr[d] + atomicAdd(&g_fill[d], 1);
        g_csr2[pos] = make_int2(s, __float_as_int(g_dinv[s] * g_dinv[d]));
    }
}

// ---------------- G1: x_emb = x @ w_feat + b_feat ; acc = x_emb (pipelined) ----------
__global__ __launch_bounds__(256) void k_gemm1(const float* __restrict__ x,
                                               const float* __restrict__ w,
                                               const float* __restrict__ b) {
    __shared__ uint32_t As[128 * 20];
    __shared__ uint32_t Bs[16 * 136];
    int t = threadIdx.x, lane = t & 31, wid = t >> 5;
    int g = lane >> 2, t4 = lane & 3;
    int r0 = blockIdx.x * 128, m0 = wid * 16;
    float acc[16][4];
#pragma unroll
    for (int n = 0; n < 16; n++) { acc[n][0] = acc[n][1] = acc[n][2] = acc[n][3] = 0.f; }

    int arow = t >> 2, ac = (t & 3) * 4;
    int ga0 = min(r0 + arow, N_NODES - 1), ga1 = min(r0 + arow + 64, N_NODES - 1);
    int brow = t >> 5, bc = (t & 31) * 4;

    float4 ra0 = *(const float4*)(x + (size_t)ga0 * IN_DIM + ac);
    float4 ra1 = *(const float4*)(x + (size_t)ga1 * IN_DIM + ac);
    float4 rb0 = *(const float4*)(w + brow * HID + bc);
    float4 rb1 = *(const float4*)(w + (brow + 8) * HID + bc);

    for (int c = 0; c < IN_DIM / 16; c++) {
        *(uint4*)&As[arow * 20 + ac]        = tf32c4(ra0);
        *(uint4*)&As[(arow + 64) * 20 + ac] = tf32c4(ra1);
        *(uint4*)&Bs[brow * 136 + bc]       = tf32c4(rb0);
        *(uint4*)&Bs[(brow + 8) * 136 + bc] = tf32c4(rb1);
        __syncthreads();
        if (c + 1 < IN_DIM / 16) {
            int k0 = (c + 1) * 16;
            ra0 = *(const float4*)(x + (size_t)ga0 * IN_DIM + k0 + ac);
            ra1 = *(const float4*)(x + (size_t)ga1 * IN_DIM + k0 + ac);
            rb0 = *(const float4*)(w + (k0 + brow) * HID + bc);
            rb1 = *(const float4*)(w + (k0 + brow + 8) * HID + bc);
        }
#pragma unroll
        for (int ks = 0; ks < 2; ks++) {
            int ar = (m0 + g) * 20 + ks * 8 + t4;
            uint32_t a0 = As[ar], a1 = As[ar + 160], a2 = As[ar + 4], a3 = As[ar + 164];
            const uint32_t* bp = &Bs[(ks * 8 + t4) * 136];
#pragma unroll
            for (int nt = 0; nt < 16; nt++)
                mma8(acc[nt], a0, a1, a2, a3, bp[nt * 8 + g], bp[544 + nt * 8 + g]);
        }
        __syncthreads();
    }
    int rA = r0 + m0 + g, rB = rA + 8;
#pragma unroll
    for (int nt = 0; nt < 16; nt++) {
        int cn = nt * 8 + t4 * 2;
        float b0 = b[cn], b1 = b[cn + 1];
        if (rA < N_NODES) {
            float2 v = make_float2(acc[nt][0] + b0, acc[nt][1] + b1);
            *(float2*)&g_xemb[rA * HID + cn] = v;
            *(float2*)&g_acc [rA * HID + cn] = v;
        }
        if (rB < N_NODES) {
            float2 v = make_float2(acc[nt][2] + b0, acc[nt][3] + b1);
            *(float2*)&g_xemb[rB * HID + cn] = v;
            *(float2*)&g_acc [rB * HID + cn] = v;
        }
    }
}

// ---------------- propagation: warp per node, float4 ----------------
__global__ __launch_bounds__(128) void k_prop(int step) {
    const float* cur = (step == 0) ? g_xemb : ((step == 1) ? g_curA : g_curB);
    float*       nxt = (step == 0) ? g_curA : ((step == 1) ? g_curB : g_curA);
    int d = blockIdx.x * 4 + (threadIdx.x >> 5);
    if (d >= N_NODES) return;
    int lane = threadIdx.x & 31;
    int s0 = g_rowptr[d], s1 = g_rowptr[d + 1];
    float4 sum = make_float4(0.f, 0.f, 0.f, 0.f);
    for (int j = s0; j < s1; j++) {
        int2 e = g_csr2[j];
        float v = __int_as_float(e.y);
        float4 c4v = *(const float4*)&cur[(size_t)e.x * HID + lane * 4];
        sum.x = fmaf(c4v.x, v, sum.x);
        sum.y = fmaf(c4v.y, v, sum.y);
        sum.z = fmaf(c4v.z, v, sum.z);
        sum.w = fmaf(c4v.w, v, sum.w);
    }
    size_t o = (size_t)d * HID + lane * 4;
    *(float4*)&nxt[o] = sum;
    float4 a = *(const float4*)&g_acc[o];
    a.x += sum.x; a.y += sum.y; a.z += sum.z; a.w += sum.w;
    *(float4*)&g_acc[o] = a;
}

// ---------------- Hm = softmax((x_emb @ w_hyper + gumbel)*2)  (R5 form) -------------
__global__ __launch_bounds__(256) void k_hyp(const float* __restrict__ wh,
                                             const float* __restrict__ u) {
    __shared__ uint32_t As[128 * 20];
    __shared__ uint32_t Bs[16 * 264];
    int t = threadIdx.x, lane = t & 31, wid = t >> 5;
    int g = lane >> 2, t4 = lane & 3;
    int r0 = blockIdx.x * 128, m0 = wid * 16;
    float acc[32][4];
#pragma unroll
    for (int n = 0; n < 32; n++) { acc[n][0] = acc[n][1] = acc[n][2] = acc[n][3] = 0.f; }

    for (int k0 = 0; k0 < HID; k0 += 16) {
        for (int i = t; i < 512; i += 256) {
            int row = i >> 2, c4 = (i & 3) * 4;
            int gr = min(r0 + row, N_NODES - 1);
            *(uint4*)&As[row * 20 + c4] =
                tf32c4(*(const float4*)(g_xemb + (size_t)gr * HID + k0 + c4));
        }
        for (int i = t; i < 1024; i += 256) {
            int row = i >> 6, c4 = (i & 63) * 4;
            *(uint4*)&Bs[row * 264 + c4] =
                tf32c4(*(const float4*)(wh + (k0 + row) * HYP + c4));
        }
        __syncthreads();
#pragma unroll
        for (int ks = 0; ks < 2; ks++) {
            int ar = (m0 + g) * 20 + ks * 8 + t4;
            uint32_t a0 = As[ar], a1 = As[ar + 160], a2 = As[ar + 4], a3 = As[ar + 164];
            const uint32_t* bp = &Bs[(ks * 8 + t4) * 264];
#pragma unroll
            for (int nt = 0; nt < 32; nt++)
                mma8(acc[nt], a0, a1, a2, a3, bp[nt * 8 + g], bp[1056 + nt * 8 + g]);
        }
        __syncthreads();
    }

    int rA = r0 + m0 + g, rB = rA + 8;
    int uA = min(rA, N_NODES - 1), uB = min(rB, N_NODES - 1);
    float mA = -1e30f, mB = -1e30f;
#pragma unroll
    for (int nt = 0; nt < 32; nt++) {
        int cn = nt * 8 + t4 * 2;
        float2 ua = *(const float2*)(u + (size_t)uA * HYP + cn);
        float2 ub = *(const float2*)(u + (size_t)uB * HYP + cn);
        acc[nt][0] = (acc[nt][0] - __logf(-logf(ua.x + EPSV) + EPSV)) * 2.f;
        acc[nt][1] = (acc[nt][1] - __logf(-logf(ua.y + EPSV) + EPSV)) * 2.f;
        acc[nt][2] = (acc[nt][2] - __logf(-logf(ub.x + EPSV) + EPSV)) * 2.f;
        acc[nt][3] = (acc[nt][3] - __logf(-logf(ub.y + EPSV) + EPSV)) * 2.f;
        mA = fmaxf(mA, fmaxf(acc[nt][0], acc[nt][1]));
        mB = fmaxf(mB, fmaxf(acc[nt][2], acc[nt][3]));
    }
    mA = fmaxf(mA, __shfl_xor_sync(0xffffffffu, mA, 1));
    mA = fmaxf(mA, __shfl_xor_sync(0xffffffffu, mA, 2));
    mB = fmaxf(mB, __shfl_xor_sync(0xffffffffu, mB, 1));
    mB = fmaxf(mB, __shfl_xor_sync(0xffffffffu, mB, 2));
    float sA = 0.f, sB = 0.f;
#pragma unroll
    for (int nt = 0; nt < 32; nt++) {
        acc[nt][0] = __expf(acc[nt][0] - mA);
        acc[nt][1] = __expf(acc[nt][1] - mA);
        acc[nt][2] = __expf(acc[nt][2] - mB);
        acc[nt][3] = __expf(acc[nt][3] - mB);
        sA += acc[nt][0] + acc[nt][1];
        sB += acc[nt][2] + acc[nt][3];
    }
    sA += __shfl_xor_sync(0xffffffffu, sA, 1);
    sA += __shfl_xor_sync(0xffffffffu, sA, 2);
    sB += __shfl_xor_sync(0xffffffffu, sB, 1);
    sB += __shfl_xor_sync(0xffffffffu, sB, 2);
    float iA = 1.f / sA, iB = 1.f / sB;
#pragma unroll
    for (int nt = 0; nt < 32; nt++) {
        int cn = nt * 8 + t4 * 2;
        if (rA < N_NODES)
            *(float2*)&g_Hm[(size_t)rA * HYP + cn] = make_float2(acc[nt][0] * iA, acc[nt][1] * iA);
        if (rB < N_NODES)
            *(float2*)&g_Hm[(size_t)rB * HYP + cn] = make_float2(acc[nt][2] * iB, acc[nt][3] * iB);
    }
}

// ---------------- lat partials: latP[b] = Hm[rows_b]^T @ xemb[rows_b] (pipelined) -----
__global__ __launch_bounds__(512) void k_lat() {
    __shared__ uint32_t Hs[16 * 264];
    __shared__ uint32_t Xs[16 * 136];
    int t = threadIdx.x, lane = t & 31, wid = t >> 5;
    int g = lane >> 2, t4 = lane & 3;
    int h0 = wid * 16;
    int base = blockIdx.x * NPB;
    float acc[16][4];
#pragma unroll
    for (int n = 0; n < 16; n++) { acc[n][0] = acc[n][1] = acc[n][2] = acc[n][3] = 0.f; }

    int hrow = t >> 6, hc = (t & 63) * 4;     // rows 0..7, +8
    int xrow = t >> 5, xc = (t & 31) * 4;     // rows 0..15

    float4 rh0, rh1, rx;
    {
        int n0 = base + hrow, n1 = base + hrow + 8, n2 = base + xrow;
        rh0 = (n0 < N_NODES) ? *(const float4*)&g_Hm[(size_t)n0 * HYP + hc] : make_float4(0,0,0,0);
        rh1 = (n1 < N_NODES) ? *(const float4*)&g_Hm[(size_t)n1 * HYP + hc] : make_float4(0,0,0,0);
        rx  = (n2 < N_NODES) ? *(const float4*)&g_xemb[(size_t)n2 * HID + xc] : make_float4(0,0,0,0);
    }

    for (int c = 0; c < NPB; c += 16) {
        *(uint4*)&Hs[hrow * 264 + hc]       = tf32c4(rh0);
        *(uint4*)&Hs[(hrow + 8) * 264 + hc] = tf32c4(rh1);
        *(uint4*)&Xs[xrow * 136 + xc]       = tf32c4(rx);
        __syncthreads();
        if (c + 16 < NPB) {
            int n0 = base + c + 16 + hrow, n1 = n0 + 8, n2 = base + c + 16 + xrow;
            rh0 = (n0 < N_NODES) ? *(const float4*)&g_Hm[(size_t)n0 * HYP + hc] : make_float4(0,0,0,0);
            rh1 = (n1 < N_NODES) ? *(const float4*)&g_Hm[(size_t)n1 * HYP + hc] : make_float4(0,0,0,0);
            rx  = (n2 < N_NODES) ? *(const float4*)&g_xemb[(size_t)n2 * HID + xc] : make_float4(0,0,0,0);
        }
#pragma unroll
        for (int ks = 0; ks < 2; ks++) {
            const uint32_t* hp  = &Hs[(ks * 8 + t4) * 264];
            const uint32_t* hp4 = hp + 4 * 264;
            uint32_t a0 = hp[h0 + g],  a1 = hp[h0 + g + 8];
            uint32_t a2 = hp4[h0 + g], a3 = hp4[h0 + g + 8];
            const uint32_t* bp = &Xs[(ks * 8 + t4) * 136];
#pragma unroll
            for (int nt = 0; nt < 16; nt++)
                mma8(acc[nt], a0, a1, a2, a3, bp[nt * 8 + g], bp[544 + nt * 8 + g]);
        }
        __syncthreads();
    }
    float* pb = &g_latP[(size_t)blockIdx.x * HYP * HID];
#pragma unroll
    for (int nt = 0; nt < 16; nt++) {
        int cn = nt * 8 + t4 * 2;
        *(float2*)&pb[(h0 + g) * HID + cn]     = make_float2(acc[nt][0], acc[nt][1]);
        *(float2*)&pb[(h0 + g + 8) * HID + cn] = make_float2(acc[nt][2], acc[nt][3]);
    }
}

__global__ void k_latred() {
    int i = blockIdx.x * blockDim.x + threadIdx.x;
    if (i < HYP * HID) {
        float s = 0.f;
        for (int b = 0; b < LATB; b++) s += g_latP[(size_t)b * HYP * HID + i];
        g_lat[i] = s;
    }
}

// ---------------- final = acc/4 + 0.1*normalize(Hm @ lat)  (R5 form) ----------------
__global__ __launch_bounds__(256) void k_final(float* __restrict__ outF) {
    __shared__ uint32_t As[128 * 20];
    __shared__ uint32_t Bs[16 * 136];
    int t = threadIdx.x, lane = t & 31, wid = t >> 5;
    int g = lane >> 2, t4 = lane & 3;
    int r0 = blockIdx.x * 128, m0 = wid * 16;
    float acc[16][4];
#pragma unroll
    for (int n = 0; n < 16; n++) { acc[n][0] = acc[n][1] = acc[n][2] = acc[n][3] = 0.f; }

    for (int k0 = 0; k0 < HYP; k0 += 16) {
        for (int i = t; i < 512; i += 256) {
            int row = i >> 2, c4 = (i & 3) * 4;
            int gr = min(r0 + row, N_NODES - 1);
            *(uint4*)&As[row * 20 + c4] =
                tf32c4(*(const float4*)(g_Hm + (size_t)gr * HYP + k0 + c4));
        }
        for (int i = t; i < 512; i += 256) {
            int row = i >> 5, c4 = (i & 31) * 4;
            *(uint4*)&Bs[row * 136 + c4] =
                tf32c4(*(const float4*)(g_lat + (k0 + row) * HID + c4));
        }
        __syncthreads();
#pragma unroll
        for (int ks = 0; ks < 2; ks++) {
            int ar = (m0 + g) * 20 + ks * 8 + t4;
            uint32_t a0 = As[ar], a1 = As[ar + 160], a2 = As[ar + 4], a3 = As[ar + 164];
            const uint32_t* bp = &Bs[(ks * 8 + t4) * 136];
#pragma unroll
            for (int nt = 0; nt < 16; nt++)
                mma8(acc[nt], a0, a1, a2, a3, bp[nt * 8 + g], bp[544 + nt * 8 + g]);
        }
        __syncthreads();
    }

    float ssA = 0.f, ssB = 0.f;
#pragma unroll
    for (int nt = 0; nt < 16; nt++) {
        ssA += acc[nt][0] * acc[nt][0] + acc[nt][1] * acc[nt][1];
        ssB += acc[nt][2] * acc[nt][2] + acc[nt][3] * acc[nt][3];
    }
    ssA += __shfl_xor_sync(0xffffffffu, ssA, 1);
    ssA += __shfl_xor_sync(0xffffffffu, ssA, 2);
    ssB += __shfl_xor_sync(0xffffffffu, ssB, 1);
    ssB += __shfl_xor_sync(0xffffffffu, ssB, 2);
    float iA = 0.1f / fmaxf(sqrtf(ssA), 1e-12f);
    float iB = 0.1f / fmaxf(sqrtf(ssB), 1e-12f);
    int rA = r0 + m0 + g, rB = rA + 8;
#pragma unroll
    for (int nt = 0; nt < 16; nt++) {
        int cn = nt * 8 + t4 * 2;
        if (rA < N_NODES) {
            float2 ag = *(const float2*)&g_acc[rA * HID + cn];
            *(float2*)&outF[(size_t)rA * HID + cn] =
                make_float2(ag.x * 0.25f + acc[nt][0] * iA, ag.y * 0.25f + acc[nt][1] * iA);
        }
        if (rB < N_NODES) {
            float2 ag = *(const float2*)&g_acc[rB * HID + cn];
            *(float2*)&outF[(size_t)rB * HID + cn] =
                make_float2(ag.x * 0.25f + acc[nt][2] * iB, ag.y * 0.25f + acc[nt][3] * iB);
        }
    }
}

// ---------------- vis/txt = relu(final @ [wv|wt] + [bv|bt])  (R5 form) ----------------
__global__ __launch_bounds__(256) void k_out(const float* __restrict__ fin,
                                             const float* __restrict__ wv, const float* __restrict__ bv,
                                             const float* __restrict__ wt, const float* __restrict__ bt,
                                             float* __restrict__ vis, float* __restrict__ txt) {
    __shared__ uint32_t As[64 * 20];
    __shared__ uint32_t Bs[16 * 264];
    int t = threadIdx.x, lane = t & 31, wid = t >> 5;
    int g = lane >> 2, t4 = lane & 3;
    int mt = wid & 3, half = wid >> 2;
    int r0 = blockIdx.x * 64, m0 = mt * 16;
    float acc[16][4];
#pragma unroll
    for (int n = 0; n < 16; n++) { acc[n][0] = acc[n][1] = acc[n][2] = acc[n][3] = 0.f; }

    for (int k0 = 0; k0 < HID; k0 += 16) {
        {
            int i = t;
            int row = i >> 2, c4 = (i & 3) * 4;
            int gr = min(r0 + row, N_NODES - 1);
            *(uint4*)&As[row * 20 + c4] =
                tf32c4(*(const float4*)(fin + (size_t)gr * HID + k0 + c4));
        }
        for (int i = t; i < 1024; i += 256) {
            int row = i >> 6, c4 = (i & 63) * 4;
            const float* srcp = (c4 < 128) ? (wv + (k0 + row) * HID + c4)
                                           : (wt + (k0 + row) * HID + (c4 - 128));
            *(uint4*)&Bs[row * 264 + c4] = tf32c4(*(const float4*)srcp);
        }
        __syncthreads();
#pragma unroll
        for (int ks = 0; ks < 2; ks++) {
            int ar = (m0 + g) * 20 + ks * 8 + t4;
            uint32_t a0 = As[ar], a1 = As[ar + 160], a2 = As[ar + 4], a3 = As[ar + 164];
            const uint32_t* bp = &Bs[(ks * 8 + t4) * 264 + half * 128];
#pragma unroll
            for (int nt = 0; nt < 16; nt++)
                mma8(acc[nt], a0, a1, a2, a3, bp[nt * 8 + g], bp[1056 + nt * 8 + g]);
        }
        __syncthreads();
    }

    const float* bias = half ? bt : bv;
    float* o = half ? txt : vis;
    int rA = r0 + m0 + g, rB = rA + 8;
#pragma unroll
    for (int nt = 0; nt < 16; nt++) {
        int cn = nt * 8 + t4 * 2;
        float b0 = bias[cn], b1 = bias[cn + 1];
        if (rA < N_NODES)
            *(float2*)&o[(size_t)rA * HID + cn] =
                make_float2(fmaxf(acc[nt][0] + b0, 0.f), fmaxf(acc[nt][1] + b1, 0.f));
        if (rB < N_NODES)
            *(float2*)&o[(size_t)rB * HID + cn] =
                make_float2(fmaxf(acc[nt][2] + b0, 0.f), fmaxf(acc[nt][3] + b1, 0.f));
    }
}

// ---------------- launcher ----------------
extern "C" void kernel_launch(void* const* d_in, const int* in_sizes, int n_in,
                              void* d_out, int out_size) {
    const float* x       = (const float*)d_in[0];
    const int*   ei      = (const int*)  d_in[1];
    const float* u       = (const float*)d_in[2];
    const float* w_feat  = (const float*)d_in[3];
    const float* b_feat  = (const float*)d_in[4];
    const float* w_hyper = (const float*)d_in[5];
    const float* w_vis   = (const float*)d_in[6];
    const float* b_vis   = (const float*)d_in[7];
    const float* w_txt   = (const float*)d_in[8];
    const float* b_txt   = (const float*)d_in[9];

    float* out  = (float*)d_out;
    float* outF = out;
    float* outV = out + (size_t)N_NODES * HID;
    float* outT = out + (size_t)2 * N_NODES * HID;

    const int* src = ei;
    const int* dst = ei + N_EDGES;

    int nb = (N_NODES + 1023) / 1024;         // 49
    int g128 = (N_NODES + 127) / 128;         // 391
    int g64  = (N_NODES + 63) / 64;           // 782

    k_zero <<<(N_NODES + 255) / 256, 256>>>();
    k_deg  <<<(N_EDGES + 255) / 256, 256>>>(dst);
    k_scan1<<<nb, 1024>>>();
    k_scan2<<<1, 64>>>(nb);
    k_scan3<<<nb, 1024>>>();
    k_fill <<<(N_EDGES + 255) / 256, 256>>>(src, dst);

    k_gemm1<<<g128, 256>>>(x, w_feat, b_feat);

    k_prop<<<(N_NODES + 3) / 4, 128>>>(0);
    k_prop<<<(N_NODES + 3) / 4, 128>>>(1);
    k_prop<<<(N_NODES + 3) / 4, 128>>>(2);

    k_hyp<<<g128, 256>>>(w_hyper, u);

    k_lat<<<LATB, 512>>>();
    k_latred<<<(HYP * HID + 1023) / 1024, 1024>>>();

    k_final<<<g128, 256>>>(outF);
    k_out  <<<g64, 256>>>(outF, w_vis, b_vis, w_txt, b_txt, outV, outT);
}

// round 14
// speedup vs baseline: 1.4139x; 1.1325x over previous
#include <cuda_runtime.h>
#include <math.h>
#include <stdint.h>

#define N_NODES 50000
#define N_EDGES 600000
#define IN_DIM  384
#define HID     128
#define HYP     256
#define EPSV    1e-10f
#define LATB    143
#define NPB     352          // 143*352 = 50336 >= 50000

// ---------------- scratch ----------------
__device__ float g_xemb[N_NODES * HID];
__device__ float g_acc [N_NODES * HID];
__device__ float g_curA[N_NODES * HID];
__device__ float g_curB[N_NODES * HID];
__device__ float g_Hm  [N_NODES * HYP];
__device__ float g_lat [HYP * HID];
__device__ float g_latP[LATB * HYP * HID];
__device__ float g_dinv[N_NODES];
__device__ int2  g_csr2[N_EDGES];
__device__ int   g_deg [N_NODES];
__device__ int   g_rowptr[N_NODES + 1];
__device__ int   g_fill[N_NODES];
__device__ int   g_part[64];

// ---------------- tf32 mma helpers ----------------
__device__ __forceinline__ uint32_t tf32c(float f) {
    uint32_t r;
    asm("cvt.rna.tf32.f32 %0, %1;" : "=r"(r) : "f"(f));
    return r;
}

__device__ __forceinline__ uint4 tf32c4(float4 v) {
    uint4 r;
    r.x = tf32c(v.x); r.y = tf32c(v.y); r.z = tf32c(v.z); r.w = tf32c(v.w);
    return r;
}

__device__ __forceinline__ void mma8(float* c,
                                     uint32_t a0, uint32_t a1, uint32_t a2, uint32_t a3,
                                     uint32_t b0, uint32_t b1) {
    asm volatile(
        "mma.sync.aligned.m16n8k8.row.col.f32.tf32.tf32.f32 "
        "{%0,%1,%2,%3},{%4,%5,%6,%7},{%8,%9},{%0,%1,%2,%3};"
        : "+f"(c[0]), "+f"(c[1]), "+f"(c[2]), "+f"(c[3])
        : "r"(a0), "r"(a1), "r"(a2), "r"(a3), "r"(b0), "r"(b1));
}

// ---------------- setup kernels ----------------
__global__ void k_zero() {
    int i = blockIdx.x * blockDim.x + threadIdx.x;
    if (i < N_NODES) { g_deg[i] = 0; g_fill[i] = 0; }
}

__global__ void k_deg(const int* __restrict__ dst) {
    int e = blockIdx.x * blockDim.x + threadIdx.x;
    if (e < N_EDGES) atomicAdd(&g_deg[dst[e]], 1);
}

__global__ void k_scan1() {
    __shared__ int sh[1024];
    int i = blockIdx.x * 1024 + threadIdx.x;
    int v = (i < N_NODES) ? g_deg[i] : 0;
    sh[threadIdx.x] = v;
    __syncthreads();
    for (int off = 1; off < 1024; off <<= 1) {
        int t = (threadIdx.x >= off) ? sh[threadIdx.x - off] : 0;
        __syncthreads();
        sh[threadIdx.x] += t;
        __syncthreads();
    }
    if (i < N_NODES) g_rowptr[i] = sh[threadIdx.x] - v;
    if (threadIdx.x == 1023) g_part[blockIdx.x] = sh[1023];
}

__global__ void k_scan2(int nb) {
    __shared__ int sh[64];
    int v = (threadIdx.x < nb) ? g_part[threadIdx.x] : 0;
    sh[threadIdx.x] = v;
    __syncthreads();
    for (int off = 1; off < 64; off <<= 1) {
        int t = (threadIdx.x >= off) ? sh[threadIdx.x - off] : 0;
        __syncthreads();
        sh[threadIdx.x] += t;
        __syncthreads();
    }
    if (threadIdx.x < nb) g_part[threadIdx.x] = sh[threadIdx.x] - v;
}

// scan finalize + dinv fused
__global__ void k_scan3() {
    int i = blockIdx.x * 1024 + threadIdx.x;
    if (i < N_NODES) {
        g_rowptr[i] += g_part[blockIdx.x];
        int d = g_deg[i];
        g_dinv[i] = (d > 0) ? rsqrtf((float)d) : 0.f;
    }
    if (i == 0) g_rowptr[N_NODES] = N_EDGES;
}

__global__ void k_fill(const int* __restrict__ src, const int* __restrict__ dst) {
    int e = blockIdx.x * blockDim.x + threadIdx.x;
    if (e < N_EDGES) {
        int d = dst[e], s = src[e];
        int pos = g_rowptr[d] + atomicAdd(&g_fill[d], 1);
        g_csr2[pos] = make_int2(s, __float_as_int(g_dinv[s] * g_dinv[d]));
    }
}

// ---------------- G1: x_emb = x @ w_feat + b_feat ; acc = x_emb (pipelined) ----------
__global__ __launch_bounds__(256) void k_gemm1(const float* __restrict__ x,
                                               const float* __restrict__ w,
                                               const float* __restrict__ b) {
    __shared__ uint32_t As[128 * 20];
    __shared__ uint32_t Bs[16 * 136];
    int t = threadIdx.x, lane = t & 31, wid = t >> 5;
    int g = lane >> 2, t4 = lane & 3;
    int r0 = blockIdx.x * 128, m0 = wid * 16;
    float acc[16][4];
#pragma unroll
    for (int n = 0; n < 16; n++) { acc[n][0] = acc[n][1] = acc[n][2] = acc[n][3] = 0.f; }

    int arow = t >> 2, ac = (t & 3) * 4;
    int ga0 = min(r0 + arow, N_NODES - 1), ga1 = min(r0 + arow + 64, N_NODES - 1);
    int brow = t >> 5, bc = (t & 31) * 4;

    float4 ra0 = *(const float4*)(x + (size_t)ga0 * IN_DIM + ac);
    float4 ra1 = *(const float4*)(x + (size_t)ga1 * IN_DIM + ac);
    float4 rb0 = *(const float4*)(w + brow * HID + bc);
    float4 rb1 = *(const float4*)(w + (brow + 8) * HID + bc);

    for (int c = 0; c < IN_DIM / 16; c++) {
        *(uint4*)&As[arow * 20 + ac]        = tf32c4(ra0);
        *(uint4*)&As[(arow + 64) * 20 + ac] = tf32c4(ra1);
        *(uint4*)&Bs[brow * 136 + bc]       = tf32c4(rb0);
        *(uint4*)&Bs[(brow + 8) * 136 + bc] = tf32c4(rb1);
        __syncthreads();
        if (c + 1 < IN_DIM / 16) {
            int k0 = (c + 1) * 16;
            ra0 = *(const float4*)(x + (size_t)ga0 * IN_DIM + k0 + ac);
            ra1 = *(const float4*)(x + (size_t)ga1 * IN_DIM + k0 + ac);
            rb0 = *(const float4*)(w + (k0 + brow) * HID + bc);
            rb1 = *(const float4*)(w + (k0 + brow + 8) * HID + bc);
        }
#pragma unroll
        for (int ks = 0; ks < 2; ks++) {
            int ar = (m0 + g) * 20 + ks * 8 + t4;
            uint32_t a0 = As[ar], a1 = As[ar + 160], a2 = As[ar + 4], a3 = As[ar + 164];
            const uint32_t* bp = &Bs[(ks * 8 + t4) * 136];
#pragma unroll
            for (int nt = 0; nt < 16; nt++)
                mma8(acc[nt], a0, a1, a2, a3, bp[nt * 8 + g], bp[544 + nt * 8 + g]);
        }
        __syncthreads();
    }
    int rA = r0 + m0 + g, rB = rA + 8;
#pragma unroll
    for (int nt = 0; nt < 16; nt++) {
        int cn = nt * 8 + t4 * 2;
        float b0 = b[cn], b1 = b[cn + 1];
        if (rA < N_NODES) {
            float2 v = make_float2(acc[nt][0] + b0, acc[nt][1] + b1);
            *(float2*)&g_xemb[rA * HID + cn] = v;
            *(float2*)&g_acc [rA * HID + cn] = v;
        }
        if (rB < N_NODES) {
            float2 v = make_float2(acc[nt][2] + b0, acc[nt][3] + b1);
            *(float2*)&g_xemb[rB * HID + cn] = v;
            *(float2*)&g_acc [rB * HID + cn] = v;
        }
    }
}

// ---------------- propagation: warp per node, float4 ----------------
__global__ __launch_bounds__(128) void k_prop(int step) {
    const float* cur = (step == 0) ? g_xemb : ((step == 1) ? g_curA : g_curB);
    float*       nxt = (step == 0) ? g_curA : ((step == 1) ? g_curB : g_curA);
    int d = blockIdx.x * 4 + (threadIdx.x >> 5);
    if (d >= N_NODES) return;
    int lane = threadIdx.x & 31;
    int s0 = g_rowptr[d], s1 = g_rowptr[d + 1];
    float4 sum = make_float4(0.f, 0.f, 0.f, 0.f);
    for (int j = s0; j < s1; j++) {
        int2 e = g_csr2[j];
        float v = __int_as_float(e.y);
        float4 c4v = *(const float4*)&cur[(size_t)e.x * HID + lane * 4];
        sum.x = fmaf(c4v.x, v, sum.x);
        sum.y = fmaf(c4v.y, v, sum.y);
        sum.z = fmaf(c4v.z, v, sum.z);
        sum.w = fmaf(c4v.w, v, sum.w);
    }
    size_t o = (size_t)d * HID + lane * 4;
    *(float4*)&nxt[o] = sum;
    float4 a = *(const float4*)&g_acc[o];
    a.x += sum.x; a.y += sum.y; a.z += sum.z; a.w += sum.w;
    *(float4*)&g_acc[o] = a;
}

// ------- Hm = softmax((x_emb @ w_hyper + gumbel)*2); M=64 tile, warp-pair N-split -----
__global__ __launch_bounds__(256) void k_hyp(const float* __restrict__ wh_,
                                             const float* __restrict__ u) {
    __shared__ uint32_t As[64 * 20];
    __shared__ uint32_t Bs[16 * 264];
    __shared__ float redM[4][8][2][2];   // [wq][g][AB][wh]
    __shared__ float redS[4][8][2][2];
    int t = threadIdx.x, lane = t & 31, wid = t >> 5;
    int g = lane >> 2, t4 = lane & 3;
    int wq = wid & 3, wh = wid >> 2;     // row-group / column-half
    int r0 = blockIdx.x * 64, m0 = wq * 16;
    float acc[16][4];
#pragma unroll
    for (int n = 0; n < 16; n++) { acc[n][0] = acc[n][1] = acc[n][2] = acc[n][3] = 0.f; }

    for (int k0 = 0; k0 < HID; k0 += 16) {
        {
            int i = t;  // 256 float4, one per thread: 64 rows x 16 cols
            int row = i >> 2, c4 = (i & 3) * 4;
            int gr = min(r0 + row, N_NODES - 1);
            *(uint4*)&As[row * 20 + c4] =
                tf32c4(*(const float4*)(g_xemb + (size_t)gr * HID + k0 + c4));
        }
        for (int i = t; i < 1024; i += 256) {
            int row = i >> 6, c4 = (i & 63) * 4;
            *(uint4*)&Bs[row * 264 + c4] =
                tf32c4(*(const float4*)(wh_ + (k0 + row) * HYP + c4));
        }
        __syncthreads();
#pragma unroll
        for (int ks = 0; ks < 2; ks++) {
            int ar = (m0 + g) * 20 + ks * 8 + t4;
            uint32_t a0 = As[ar], a1 = As[ar + 160], a2 = As[ar + 4], a3 = As[ar + 164];
            const uint32_t* bp = &Bs[(ks * 8 + t4) * 264 + wh * 128];
#pragma unroll
            for (int nt = 0; nt < 16; nt++)
                mma8(acc[nt], a0, a1, a2, a3, bp[nt * 8 + g], bp[1056 + nt * 8 + g]);
        }
        __syncthreads();
    }

    int rA = r0 + m0 + g, rB = rA + 8;
    int uA = min(rA, N_NODES - 1), uB = min(rB, N_NODES - 1);
    int cb = wh * 128;
    float mA = -1e30f, mB = -1e30f;
#pragma unroll
    for (int nt = 0; nt < 16; nt++) {
        int cn = cb + nt * 8 + t4 * 2;
        float2 ua = *(const float2*)(u + (size_t)uA * HYP + cn);
        float2 ub = *(const float2*)(u + (size_t)uB * HYP + cn);
        acc[nt][0] = (acc[nt][0] - __logf(-logf(ua.x + EPSV) + EPSV)) * 2.f;
        acc[nt][1] = (acc[nt][1] - __logf(-logf(ua.y + EPSV) + EPSV)) * 2.f;
        acc[nt][2] = (acc[nt][2] - __logf(-logf(ub.x + EPSV) + EPSV)) * 2.f;
        acc[nt][3] = (acc[nt][3] - __logf(-logf(ub.y + EPSV) + EPSV)) * 2.f;
        mA = fmaxf(mA, fmaxf(acc[nt][0], acc[nt][1]));
        mB = fmaxf(mB, fmaxf(acc[nt][2], acc[nt][3]));
    }
    mA = fmaxf(mA, __shfl_xor_sync(0xffffffffu, mA, 1));
    mA = fmaxf(mA, __shfl_xor_sync(0xffffffffu, mA, 2));
    mB = fmaxf(mB, __shfl_xor_sync(0xffffffffu, mB, 1));
    mB = fmaxf(mB, __shfl_xor_sync(0xffffffffu, mB, 2));
    if (t4 == 0) { redM[wq][g][0][wh] = mA; redM[wq][g][1][wh] = mB; }
    __syncthreads();
    mA = fmaxf(redM[wq][g][0][0], redM[wq][g][0][1]);
    mB = fmaxf(redM[wq][g][1][0], redM[wq][g][1][1]);

    float sA = 0.f, sB = 0.f;
#pragma unroll
    for (int nt = 0; nt < 16; nt++) {
        acc[nt][0] = __expf(acc[nt][0] - mA);
        acc[nt][1] = __expf(acc[nt][1] - mA);
        acc[nt][2] = __expf(acc[nt][2] - mB);
        acc[nt][3] = __expf(acc[nt][3] - mB);
        sA += acc[nt][0] + acc[nt][1];
        sB += acc[nt][2] + acc[nt][3];
    }
    sA += __shfl_xor_sync(0xffffffffu, sA, 1);
    sA += __shfl_xor_sync(0xffffffffu, sA, 2);
    sB += __shfl_xor_sync(0xffffffffu, sB, 1);
    sB += __shfl_xor_sync(0xffffffffu, sB, 2);
    if (t4 == 0) { redS[wq][g][0][wh] = sA; redS[wq][g][1][wh] = sB; }
    __syncthreads();
    float iA = 1.f / (redS[wq][g][0][0] + redS[wq][g][0][1]);
    float iB = 1.f / (redS[wq][g][1][0] + redS[wq][g][1][1]);

#pragma unroll
    for (int nt = 0; nt < 16; nt++) {
        int cn = cb + nt * 8 + t4 * 2;
        if (rA < N_NODES)
            *(float2*)&g_Hm[(size_t)rA * HYP + cn] = make_float2(acc[nt][0] * iA, acc[nt][1] * iA);
        if (rB < N_NODES)
            *(float2*)&g_Hm[(size_t)rB * HYP + cn] = make_float2(acc[nt][2] * iB, acc[nt][3] * iB);
    }
}

// ---------------- lat partials: latP[b] = Hm[rows_b]^T @ xemb[rows_b] (pipelined) -----
__global__ __launch_bounds__(512) void k_lat() {
    __shared__ uint32_t Hs[16 * 264];
    __shared__ uint32_t Xs[16 * 136];
    int t = threadIdx.x, lane = t & 31, wid = t >> 5;
    int g = lane >> 2, t4 = lane & 3;
    int h0 = wid * 16;
    int base = blockIdx.x * NPB;
    float acc[16][4];
#pragma unroll
    for (int n = 0; n < 16; n++) { acc[n][0] = acc[n][1] = acc[n][2] = acc[n][3] = 0.f; }

    int hrow = t >> 6, hc = (t & 63) * 4;
    int xrow = t >> 5, xc = (t & 31) * 4;

    float4 rh0, rh1, rx;
    {
        int n0 = base + hrow, n1 = base + hrow + 8, n2 = base + xrow;
        rh0 = (n0 < N_NODES) ? *(const float4*)&g_Hm[(size_t)n0 * HYP + hc] : make_float4(0,0,0,0);
        rh1 = (n1 < N_NODES) ? *(const float4*)&g_Hm[(size_t)n1 * HYP + hc] : make_float4(0,0,0,0);
        rx  = (n2 < N_NODES) ? *(const float4*)&g_xemb[(size_t)n2 * HID + xc] : make_float4(0,0,0,0);
    }

    for (int c = 0; c < NPB; c += 16) {
        *(uint4*)&Hs[hrow * 264 + hc]       = tf32c4(rh0);
        *(uint4*)&Hs[(hrow + 8) * 264 + hc] = tf32c4(rh1);
        *(uint4*)&Xs[xrow * 136 + xc]       = tf32c4(rx);
        __syncthreads();
        if (c + 16 < NPB) {
            int n0 = base + c + 16 + hrow, n1 = n0 + 8, n2 = base + c + 16 + xrow;
            rh0 = (n0 < N_NODES) ? *(const float4*)&g_Hm[(size_t)n0 * HYP + hc] : make_float4(0,0,0,0);
            rh1 = (n1 < N_NODES) ? *(const float4*)&g_Hm[(size_t)n1 * HYP + hc] : make_float4(0,0,0,0);
            rx  = (n2 < N_NODES) ? *(const float4*)&g_xemb[(size_t)n2 * HID + xc] : make_float4(0,0,0,0);
        }
#pragma unroll
        for (int ks = 0; ks < 2; ks++) {
            const uint32_t* hp  = &Hs[(ks * 8 + t4) * 264];
            const uint32_t* hp4 = hp + 4 * 264;
            uint32_t a0 = hp[h0 + g],  a1 = hp[h0 + g + 8];
            uint32_t a2 = hp4[h0 + g], a3 = hp4[h0 + g + 8];
            const uint32_t* bp = &Xs[(ks * 8 + t4) * 136];
#pragma unroll
            for (int nt = 0; nt < 16; nt++)
                mma8(acc[nt], a0, a1, a2, a3, bp[nt * 8 + g], bp[544 + nt * 8 + g]);
        }
        __syncthreads();
    }
    float* pb = &g_latP[(size_t)blockIdx.x * HYP * HID];
#pragma unroll
    for (int nt = 0; nt < 16; nt++) {
        int cn = nt * 8 + t4 * 2;
        *(float2*)&pb[(h0 + g) * HID + cn]     = make_float2(acc[nt][0], acc[nt][1]);
        *(float2*)&pb[(h0 + g + 8) * HID + cn] = make_float2(acc[nt][2], acc[nt][3]);
    }
}

__global__ void k_latred() {
    int i = blockIdx.x * blockDim.x + threadIdx.x;
    if (i < HYP * HID) {
        float s = 0.f;
        for (int b = 0; b < LATB; b++) s += g_latP[(size_t)b * HYP * HID + i];
        g_lat[i] = s;
    }
}

// ---------------- final = acc/4 + 0.1*normalize(Hm @ lat)  (pipelined) ----------------
__global__ __launch_bounds__(256) void k_final(float* __restrict__ outF) {
    __shared__ uint32_t As[128 * 20];
    __shared__ uint32_t Bs[16 * 136];
    int t = threadIdx.x, lane = t & 31, wid = t >> 5;
    int g = lane >> 2, t4 = lane & 3;
    int r0 = blockIdx.x * 128, m0 = wid * 16;
    float acc[16][4];
#pragma unroll
    for (int n = 0; n < 16; n++) { acc[n][0] = acc[n][1] = acc[n][2] = acc[n][3] = 0.f; }

    int arow = t >> 2, ac = (t & 3) * 4;
    int ga0 = min(r0 + arow, N_NODES - 1), ga1 = min(r0 + arow + 64, N_NODES - 1);
    int brow = t >> 5, bc = (t & 31) * 4;

    float4 ra0 = *(const float4*)(g_Hm + (size_t)ga0 * HYP + ac);
    float4 ra1 = *(const float4*)(g_Hm + (size_t)ga1 * HYP + ac);
    float4 rb0 = *(const float4*)(g_lat + brow * HID + bc);
    float4 rb1 = *(const float4*)(g_lat + (brow + 8) * HID + bc);

    for (int c = 0; c < HYP / 16; c++) {
        *(uint4*)&As[arow * 20 + ac]        = tf32c4(ra0);
        *(uint4*)&As[(arow + 64) * 20 + ac] = tf32c4(ra1);
        *(uint4*)&Bs[brow * 136 + bc]       = tf32c4(rb0);
        *(uint4*)&Bs[(brow + 8) * 136 + bc] = tf32c4(rb1);
        __syncthreads();
        if (c + 1 < HYP / 16) {
            int k0 = (c + 1) * 16;
            ra0 = *(const float4*)(g_Hm + (size_t)ga0 * HYP + k0 + ac);
            ra1 = *(const float4*)(g_Hm + (size_t)ga1 * HYP + k0 + ac);
            rb0 = *(const float4*)(g_lat + (k0 + brow) * HID + bc);
            rb1 = *(const float4*)(g_lat + (k0 + brow + 8) * HID + bc);
        }
#pragma unroll
        for (int ks = 0; ks < 2; ks++) {
            int ar = (m0 + g) * 20 + ks * 8 + t4;
            uint32_t a0 = As[ar], a1 = As[ar + 160], a2 = As[ar + 4], a3 = As[ar + 164];
            const uint32_t* bp = &Bs[(ks * 8 + t4) * 136];
#pragma unroll
            for (int nt = 0; nt < 16; nt++)
                mma8(acc[nt], a0, a1, a2, a3, bp[nt * 8 + g], bp[544 + nt * 8 + g]);
        }
        __syncthreads();
    }

    float ssA = 0.f, ssB = 0.f;
#pragma unroll
    for (int nt = 0; nt < 16; nt++) {
        ssA += acc[nt][0] * acc[nt][0] + acc[nt][1] * acc[nt][1];
        ssB += acc[nt][2] * acc[nt][2] + acc[nt][3] * acc[nt][3];
    }
    ssA += __shfl_xor_sync(0xffffffffu, ssA, 1);
    ssA += __shfl_xor_sync(0xffffffffu, ssA, 2);
    ssB += __shfl_xor_sync(0xffffffffu, ssB, 1);
    ssB += __shfl_xor_sync(0xffffffffu, ssB, 2);
    float iA = 0.1f / fmaxf(sqrtf(ssA), 1e-12f);
    float iB = 0.1f / fmaxf(sqrtf(ssB), 1e-12f);
    int rA = r0 + m0 + g, rB = rA + 8;
#pragma unroll
    for (int nt = 0; nt < 16; nt++) {
        int cn = nt * 8 + t4 * 2;
        if (rA < N_NODES) {
            float2 ag = *(const float2*)&g_acc[rA * HID + cn];
            *(float2*)&outF[(size_t)rA * HID + cn] =
                make_float2(ag.x * 0.25f + acc[nt][0] * iA, ag.y * 0.25f + acc[nt][1] * iA);
        }
        if (rB < N_NODES) {
            float2 ag = *(const float2*)&g_acc[rB * HID + cn];
            *(float2*)&outF[(size_t)rB * HID + cn] =
                make_float2(ag.x * 0.25f + acc[nt][2] * iB, ag.y * 0.25f + acc[nt][3] * iB);
        }
    }
}

// ---------------- vis/txt = relu(final @ [wv|wt] + [bv|bt])  (R5 form) ----------------
__global__ __launch_bounds__(256) void k_out(const float* __restrict__ fin,
                                             const float* __restrict__ wv, const float* __restrict__ bv,
                                             const float* __restrict__ wt, const float* __restrict__ bt,
                                             float* __restrict__ vis, float* __restrict__ txt) {
    __shared__ uint32_t As[64 * 20];
    __shared__ uint32_t Bs[16 * 264];
    int t = threadIdx.x, lane = t & 31, wid = t >> 5;
    int g = lane >> 2, t4 = lane & 3;
    int mt = wid & 3, half = wid >> 2;
    int r0 = blockIdx.x * 64, m0 = mt * 16;
    float acc[16][4];
#pragma unroll
    for (int n = 0; n < 16; n++) { acc[n][0] = acc[n][1] = acc[n][2] = acc[n][3] = 0.f; }

    for (int k0 = 0; k0 < HID; k0 += 16) {
        {
            int i = t;
            int row = i >> 2, c4 = (i & 3) * 4;
            int gr = min(r0 + row, N_NODES - 1);
            *(uint4*)&As[row * 20 + c4] =
                tf32c4(*(const float4*)(fin + (size_t)gr * HID + k0 + c4));
        }
        for (int i = t; i < 1024; i += 256) {
            int row = i >> 6, c4 = (i & 63) * 4;
            const float* srcp = (c4 < 128) ? (wv + (k0 + row) * HID + c4)
                                           : (wt + (k0 + row) * HID + (c4 - 128));
            *(uint4*)&Bs[row * 264 + c4] = tf32c4(*(const float4*)srcp);
        }
        __syncthreads();
#pragma unroll
        for (int ks = 0; ks < 2; ks++) {
            int ar = (m0 + g) * 20 + ks * 8 + t4;
            uint32_t a0 = As[ar], a1 = As[ar + 160], a2 = As[ar + 4], a3 = As[ar + 164];
            const uint32_t* bp = &Bs[(ks * 8 + t4) * 264 + half * 128];
#pragma unroll
            for (int nt = 0; nt < 16; nt++)
                mma8(acc[nt], a0, a1, a2, a3, bp[nt * 8 + g], bp[1056 + nt * 8 + g]);
        }
        __syncthreads();
    }

    const float* bias = half ? bt : bv;
    float* o = half ? txt : vis;
    int rA = r0 + m0 + g, rB = rA + 8;
#pragma unroll
    for (int nt = 0; nt < 16; nt++) {
        int cn = nt * 8 + t4 * 2;
        float b0 = bias[cn], b1 = bias[cn + 1];
        if (rA < N_NODES)
            *(float2*)&o[(size_t)rA * HID + cn] =
                make_float2(fmaxf(acc[nt][0] + b0, 0.f), fmaxf(acc[nt][1] + b1, 0.f));
        if (rB < N_NODES)
            *(float2*)&o[(size_t)rB * HID + cn] =
                make_float2(fmaxf(acc[nt][2] + b0, 0.f), fmaxf(acc[nt][3] + b1, 0.f));
    }
}

// ---------------- launcher ----------------
extern "C" void kernel_launch(void* const* d_in, const int* in_sizes, int n_in,
                              void* d_out, int out_size) {
    const float* x       = (const float*)d_in[0];
    const int*   ei      = (const int*)  d_in[1];
    const float* u       = (const float*)d_in[2];
    const float* w_feat  = (const float*)d_in[3];
    const float* b_feat  = (const float*)d_in[4];
    const float* w_hyper = (const float*)d_in[5];
    const float* w_vis   = (const float*)d_in[6];
    const float* b_vis   = (const float*)d_in[7];
    const float* w_txt   = (const float*)d_in[8];
    const float* b_txt   = (const float*)d_in[9];

    float* out  = (float*)d_out;
    float* outF = out;
    float* outV = out + (size_t)N_NODES * HID;
    float* outT = out + (size_t)2 * N_NODES * HID;

    const int* src = ei;
    const int* dst = ei + N_EDGES;

    int nb = (N_NODES + 1023) / 1024;         // 49
    int g128 = (N_NODES + 127) / 128;         // 391
    int g64  = (N_NODES + 63) / 64;           // 782

    k_zero <<<(N_NODES + 255) / 256, 256>>>();
    k_deg  <<<(N_EDGES + 255) / 256, 256>>>(dst);
    k_scan1<<<nb, 1024>>>();
    k_scan2<<<1, 64>>>(nb);
    k_scan3<<<nb, 1024>>>();
    k_fill <<<(N_EDGES + 255) / 256, 256>>>(src, dst);

    k_gemm1<<<g128, 256>>>(x, w_feat, b_feat);

    k_prop<<<(N_NODES + 3) / 4, 128>>>(0);
    k_prop<<<(N_NODES + 3) / 4, 128>>>(1);
    k_prop<<<(N_NODES + 3) / 4, 128>>>(2);

    k_hyp<<<g64, 256>>>(w_hyper, u);

    k_lat<<<LATB, 512>>>();
    k_latred<<<(HYP * HID + 1023) / 1024, 1024>>>();

    k_final<<<g128, 256>>>(outF);
    k_out  <<<g64, 256>>>(outF, w_vis, b_vis, w_txt, b_txt, outV, outT);
}

// round 15
// speedup vs baseline: 1.4988x; 1.0601x over previous
#include <cuda_runtime.h>
#include <math.h>
#include <stdint.h>

#define N_NODES 50000
#define N_EDGES 600000
#define IN_DIM  384
#define HID     128
#define HYP     256
#define EPSV    1e-10f
#define LATB    143
#define NPB     352          // 143*352 = 50336 >= 50000

// ---------------- scratch ----------------
__device__ float g_xemb[N_NODES * HID];
__device__ float g_acc [N_NODES * HID];
__device__ float g_curA[N_NODES * HID];
__device__ float g_curB[N_NODES * HID];
__device__ float g_Hm  [N_NODES * HYP];
__device__ float g_lat [HYP * HID];
__device__ float g_latP[LATB * HYP * HID];
__device__ float g_dinv[N_NODES];
__device__ int2  g_csr2[N_EDGES];
__device__ int   g_deg [N_NODES];
__device__ int   g_rowptr[N_NODES + 1];
__device__ int   g_fill[N_NODES];
__device__ int   g_part[64];

// ---------------- tf32 mma helpers ----------------
__device__ __forceinline__ uint32_t tf32c(float f) {
    uint32_t r;
    asm("cvt.rna.tf32.f32 %0, %1;" : "=r"(r) : "f"(f));
    return r;
}

__device__ __forceinline__ uint4 tf32c4(float4 v) {
    uint4 r;
    r.x = tf32c(v.x); r.y = tf32c(v.y); r.z = tf32c(v.z); r.w = tf32c(v.w);
    return r;
}

__device__ __forceinline__ void mma8(float* c,
                                     uint32_t a0, uint32_t a1, uint32_t a2, uint32_t a3,
                                     uint32_t b0, uint32_t b1) {
    asm volatile(
        "mma.sync.aligned.m16n8k8.row.col.f32.tf32.tf32.f32 "
        "{%0,%1,%2,%3},{%4,%5,%6,%7},{%8,%9},{%0,%1,%2,%3};"
        : "+f"(c[0]), "+f"(c[1]), "+f"(c[2]), "+f"(c[3])
        : "r"(a0), "r"(a1), "r"(a2), "r"(a3), "r"(b0), "r"(b1));
}

// ---------------- setup kernels ----------------
__global__ void k_zero() {
    int i = blockIdx.x * blockDim.x + threadIdx.x;
    if (i < N_NODES) { g_deg[i] = 0; g_fill[i] = 0; }
}

__global__ void k_deg(const int* __restrict__ dst) {
    int e = blockIdx.x * blockDim.x + threadIdx.x;
    if (e < N_EDGES) atomicAdd(&g_deg[dst[e]], 1);
}

__global__ void k_scan1() {
    __shared__ int sh[1024];
    int i = blockIdx.x * 1024 + threadIdx.x;
    int v = (i < N_NODES) ? g_deg[i] : 0;
    sh[threadIdx.x] = v;
    __syncthreads();
    for (int off = 1; off < 1024; off <<= 1) {
        int t = (threadIdx.x >= off) ? sh[threadIdx.x - off] : 0;
        __syncthreads();
        sh[threadIdx.x] += t;
        __syncthreads();
    }
    if (i < N_NODES) g_rowptr[i] = sh[threadIdx.x] - v;
    if (threadIdx.x == 1023) g_part[blockIdx.x] = sh[1023];
}

__global__ void k_scan2(int nb) {
    __shared__ int sh[64];
    int v = (threadIdx.x < nb) ? g_part[threadIdx.x] : 0;
    sh[threadIdx.x] = v;
    __syncthreads();
    for (int off = 1; off < 64; off <<= 1) {
        int t = (threadIdx.x >= off) ? sh[threadIdx.x - off] : 0;
        __syncthreads();
        sh[threadIdx.x] += t;
        __syncthreads();
    }
    if (threadIdx.x < nb) g_part[threadIdx.x] = sh[threadIdx.x] - v;
}

// scan finalize + dinv fused
__global__ void k_scan3() {
    int i = blockIdx.x * 1024 + threadIdx.x;
    if (i < N_NODES) {
        g_rowptr[i] += g_part[blockIdx.x];
        int d = g_deg[i];
        g_dinv[i] = (d > 0) ? rsqrtf((float)d) : 0.f;
    }
    if (i == 0) g_rowptr[N_NODES] = N_EDGES;
}

__global__ void k_fill(const int* __restrict__ src, const int* __restrict__ dst) {
    int e = blockIdx.x * blockDim.x + threadIdx.x;
    if (e < N_EDGES) {
        int d = dst[e], s = src[e];
        int pos = g_rowptr[d] + atomicAdd(&g_fill[d], 1);
        g_csr2[pos] = make_int2(s, __float_as_int(g_dinv[s] * g_dinv[d]));
    }
}

// ---------------- G1: x_emb = x @ w_feat + b_feat ; acc = x_emb (pipelined) ----------
__global__ __launch_bounds__(256) void k_gemm1(const float* __restrict__ x,
                                               const float* __restrict__ w,
                                               const float* __restrict__ b) {
    __shared__ uint32_t As[128 * 20];
    __shared__ uint32_t Bs[16 * 136];
    int t = threadIdx.x, lane = t & 31, wid = t >> 5;
    int g = lane >> 2, t4 = lane & 3;
    int r0 = blockIdx.x * 128, m0 = wid * 16;
    float acc[16][4];
#pragma unroll
    for (int n = 0; n < 16; n++) { acc[n][0] = acc[n][1] = acc[n][2] = acc[n][3] = 0.f; }

    int arow = t >> 2, ac = (t & 3) * 4;
    int ga0 = min(r0 + arow, N_NODES - 1), ga1 = min(r0 + arow + 64, N_NODES - 1);
    int brow = t >> 5, bc = (t & 31) * 4;

    float4 ra0 = *(const float4*)(x + (size_t)ga0 * IN_DIM + ac);
    float4 ra1 = *(const float4*)(x + (size_t)ga1 * IN_DIM + ac);
    float4 rb0 = *(const float4*)(w + brow * HID + bc);
    float4 rb1 = *(const float4*)(w + (brow + 8) * HID + bc);

    for (int c = 0; c < IN_DIM / 16; c++) {
        *(uint4*)&As[arow * 20 + ac]        = tf32c4(ra0);
        *(uint4*)&As[(arow + 64) * 20 + ac] = tf32c4(ra1);
        *(uint4*)&Bs[brow * 136 + bc]       = tf32c4(rb0);
        *(uint4*)&Bs[(brow + 8) * 136 + bc] = tf32c4(rb1);
        __syncthreads();
        if (c + 1 < IN_DIM / 16) {
            int k0 = (c + 1) * 16;
            ra0 = *(const float4*)(x + (size_t)ga0 * IN_DIM + k0 + ac);
            ra1 = *(const float4*)(x + (size_t)ga1 * IN_DIM + k0 + ac);
            rb0 = *(const float4*)(w + (k0 + brow) * HID + bc);
            rb1 = *(const float4*)(w + (k0 + brow + 8) * HID + bc);
        }
#pragma unroll
        for (int ks = 0; ks < 2; ks++) {
            int ar = (m0 + g) * 20 + ks * 8 + t4;
            uint32_t a0 = As[ar], a1 = As[ar + 160], a2 = As[ar + 4], a3 = As[ar + 164];
            const uint32_t* bp = &Bs[(ks * 8 + t4) * 136];
#pragma unroll
            for (int nt = 0; nt < 16; nt++)
                mma8(acc[nt], a0, a1, a2, a3, bp[nt * 8 + g], bp[544 + nt * 8 + g]);
        }
        __syncthreads();
    }
    int rA = r0 + m0 + g, rB = rA + 8;
#pragma unroll
    for (int nt = 0; nt < 16; nt++) {
        int cn = nt * 8 + t4 * 2;
        float b0 = b[cn], b1 = b[cn + 1];
        if (rA < N_NODES) {
            float2 v = make_float2(acc[nt][0] + b0, acc[nt][1] + b1);
            *(float2*)&g_xemb[rA * HID + cn] = v;
            *(float2*)&g_acc [rA * HID + cn] = v;
        }
        if (rB < N_NODES) {
            float2 v = make_float2(acc[nt][2] + b0, acc[nt][3] + b1);
            *(float2*)&g_xemb[rB * HID + cn] = v;
            *(float2*)&g_acc [rB * HID + cn] = v;
        }
    }
}

// ---------------- propagation: warp per node, float4 ----------------
__global__ __launch_bounds__(128) void k_prop(int step) {
    const float* cur = (step == 0) ? g_xemb : ((step == 1) ? g_curA : g_curB);
    float*       nxt = (step == 0) ? g_curA : ((step == 1) ? g_curB : g_curA);
    int d = blockIdx.x * 4 + (threadIdx.x >> 5);
    if (d >= N_NODES) return;
    int lane = threadIdx.x & 31;
    int s0 = g_rowptr[d], s1 = g_rowptr[d + 1];
    float4 sum = make_float4(0.f, 0.f, 0.f, 0.f);
    for (int j = s0; j < s1; j++) {
        int2 e = g_csr2[j];
        float v = __int_as_float(e.y);
        float4 c4v = *(const float4*)&cur[(size_t)e.x * HID + lane * 4];
        sum.x = fmaf(c4v.x, v, sum.x);
        sum.y = fmaf(c4v.y, v, sum.y);
        sum.z = fmaf(c4v.z, v, sum.z);
        sum.w = fmaf(c4v.w, v, sum.w);
    }
    size_t o = (size_t)d * HID + lane * 4;
    *(float4*)&nxt[o] = sum;
    float4 a = *(const float4*)&g_acc[o];
    a.x += sum.x; a.y += sum.y; a.z += sum.z; a.w += sum.w;
    *(float4*)&g_acc[o] = a;
}

// ------- Hm = softmax((x_emb @ w_hyper + gumbel)*2); M=64 tile, warp-pair N-split -----
__global__ __launch_bounds__(256) void k_hyp(const float* __restrict__ wh_,
                                             const float* __restrict__ u) {
    __shared__ uint32_t As[64 * 20];
    __shared__ uint32_t Bs[16 * 264];
    __shared__ float redM[4][8][2][2];   // [wq][g][AB][wh]
    __shared__ float redS[4][8][2][2];
    int t = threadIdx.x, lane = t & 31, wid = t >> 5;
    int g = lane >> 2, t4 = lane & 3;
    int wq = wid & 3, wh = wid >> 2;     // row-group / column-half
    int r0 = blockIdx.x * 64, m0 = wq * 16;
    float acc[16][4];
#pragma unroll
    for (int n = 0; n < 16; n++) { acc[n][0] = acc[n][1] = acc[n][2] = acc[n][3] = 0.f; }

    for (int k0 = 0; k0 < HID; k0 += 16) {
        {
            int i = t;  // 256 float4, one per thread: 64 rows x 16 cols
            int row = i >> 2, c4 = (i & 3) * 4;
            int gr = min(r0 + row, N_NODES - 1);
            *(uint4*)&As[row * 20 + c4] =
                tf32c4(*(const float4*)(g_xemb + (size_t)gr * HID + k0 + c4));
        }
        for (int i = t; i < 1024; i += 256) {
            int row = i >> 6, c4 = (i & 63) * 4;
            *(uint4*)&Bs[row * 264 + c4] =
                tf32c4(*(const float4*)(wh_ + (k0 + row) * HYP + c4));
        }
        __syncthreads();
#pragma unroll
        for (int ks = 0; ks < 2; ks++) {
            int ar = (m0 + g) * 20 + ks * 8 + t4;
            uint32_t a0 = As[ar], a1 = As[ar + 160], a2 = As[ar + 4], a3 = As[ar + 164];
            const uint32_t* bp = &Bs[(ks * 8 + t4) * 264 + wh * 128];
#pragma unroll
            for (int nt = 0; nt < 16; nt++)
                mma8(acc[nt], a0, a1, a2, a3, bp[nt * 8 + g], bp[1056 + nt * 8 + g]);
        }
        __syncthreads();
    }

    int rA = r0 + m0 + g, rB = rA + 8;
    int uA = min(rA, N_NODES - 1), uB = min(rB, N_NODES - 1);
    int cb = wh * 128;
    float mA = -1e30f, mB = -1e30f;
#pragma unroll
    for (int nt = 0; nt < 16; nt++) {
        int cn = cb + nt * 8 + t4 * 2;
        float2 ua = *(const float2*)(u + (size_t)uA * HYP + cn);
        float2 ub = *(const float2*)(u + (size_t)uB * HYP + cn);
        acc[nt][0] = (acc[nt][0] - __logf(-logf(ua.x + EPSV) + EPSV)) * 2.f;
        acc[nt][1] = (acc[nt][1] - __logf(-logf(ua.y + EPSV) + EPSV)) * 2.f;
        acc[nt][2] = (acc[nt][2] - __logf(-logf(ub.x + EPSV) + EPSV)) * 2.f;
        acc[nt][3] = (acc[nt][3] - __logf(-logf(ub.y + EPSV) + EPSV)) * 2.f;
        mA = fmaxf(mA, fmaxf(acc[nt][0], acc[nt][1]));
        mB = fmaxf(mB, fmaxf(acc[nt][2], acc[nt][3]));
    }
    mA = fmaxf(mA, __shfl_xor_sync(0xffffffffu, mA, 1));
    mA = fmaxf(mA, __shfl_xor_sync(0xffffffffu, mA, 2));
    mB = fmaxf(mB, __shfl_xor_sync(0xffffffffu, mB, 1));
    mB = fmaxf(mB, __shfl_xor_sync(0xffffffffu, mB, 2));
    if (t4 == 0) { redM[wq][g][0][wh] = mA; redM[wq][g][1][wh] = mB; }
    __syncthreads();
    mA = fmaxf(redM[wq][g][0][0], redM[wq][g][0][1]);
    mB = fmaxf(redM[wq][g][1][0], redM[wq][g][1][1]);

    float sA = 0.f, sB = 0.f;
#pragma unroll
    for (int nt = 0; nt < 16; nt++) {
        acc[nt][0] = __expf(acc[nt][0] - mA);
        acc[nt][1] = __expf(acc[nt][1] - mA);
        acc[nt][2] = __expf(acc[nt][2] - mB);
        acc[nt][3] = __expf(acc[nt][3] - mB);
        sA += acc[nt][0] + acc[nt][1];
        sB += acc[nt][2] + acc[nt][3];
    }
    sA += __shfl_xor_sync(0xffffffffu, sA, 1);
    sA += __shfl_xor_sync(0xffffffffu, sA, 2);
    sB += __shfl_xor_sync(0xffffffffu, sB, 1);
    sB += __shfl_xor_sync(0xffffffffu, sB, 2);
    if (t4 == 0) { redS[wq][g][0][wh] = sA; redS[wq][g][1][wh] = sB; }
    __syncthreads();
    float iA = 1.f / (redS[wq][g][0][0] + redS[wq][g][0][1]);
    float iB = 1.f / (redS[wq][g][1][0] + redS[wq][g][1][1]);

#pragma unroll
    for (int nt = 0; nt < 16; nt++) {
        int cn = cb + nt * 8 + t4 * 2;
        if (rA < N_NODES)
            *(float2*)&g_Hm[(size_t)rA * HYP + cn] = make_float2(acc[nt][0] * iA, acc[nt][1] * iA);
        if (rB < N_NODES)
            *(float2*)&g_Hm[(size_t)rB * HYP + cn] = make_float2(acc[nt][2] * iB, acc[nt][3] * iB);
    }
}

// ---------------- lat partials: latP[b] = Hm[rows_b]^T @ xemb[rows_b] (pipelined) -----
__global__ __launch_bounds__(512) void k_lat() {
    __shared__ uint32_t Hs[16 * 264];
    __shared__ uint32_t Xs[16 * 136];
    int t = threadIdx.x, lane = t & 31, wid = t >> 5;
    int g = lane >> 2, t4 = lane & 3;
    int h0 = wid * 16;
    int base = blockIdx.x * NPB;
    float acc[16][4];
#pragma unroll
    for (int n = 0; n < 16; n++) { acc[n][0] = acc[n][1] = acc[n][2] = acc[n][3] = 0.f; }

    int hrow = t >> 6, hc = (t & 63) * 4;
    int xrow = t >> 5, xc = (t & 31) * 4;

    float4 rh0, rh1, rx;
    {
        int n0 = base + hrow, n1 = base + hrow + 8, n2 = base + xrow;
        rh0 = (n0 < N_NODES) ? *(const float4*)&g_Hm[(size_t)n0 * HYP + hc] : make_float4(0,0,0,0);
        rh1 = (n1 < N_NODES) ? *(const float4*)&g_Hm[(size_t)n1 * HYP + hc] : make_float4(0,0,0,0);
        rx  = (n2 < N_NODES) ? *(const float4*)&g_xemb[(size_t)n2 * HID + xc] : make_float4(0,0,0,0);
    }

    for (int c = 0; c < NPB; c += 16) {
        *(uint4*)&Hs[hrow * 264 + hc]       = tf32c4(rh0);
        *(uint4*)&Hs[(hrow + 8) * 264 + hc] = tf32c4(rh1);
        *(uint4*)&Xs[xrow * 136 + xc]       = tf32c4(rx);
        __syncthreads();
        if (c + 16 < NPB) {
            int n0 = base + c + 16 + hrow, n1 = n0 + 8, n2 = base + c + 16 + xrow;
            rh0 = (n0 < N_NODES) ? *(const float4*)&g_Hm[(size_t)n0 * HYP + hc] : make_float4(0,0,0,0);
            rh1 = (n1 < N_NODES) ? *(const float4*)&g_Hm[(size_t)n1 * HYP + hc] : make_float4(0,0,0,0);
            rx  = (n2 < N_NODES) ? *(const float4*)&g_xemb[(size_t)n2 * HID + xc] : make_float4(0,0,0,0);
        }
#pragma unroll
        for (int ks = 0; ks < 2; ks++) {
            const uint32_t* hp  = &Hs[(ks * 8 + t4) * 264];
            const uint32_t* hp4 = hp + 4 * 264;
            uint32_t a0 = hp[h0 + g],  a1 = hp[h0 + g + 8];
            uint32_t a2 = hp4[h0 + g], a3 = hp4[h0 + g + 8];
            const uint32_t* bp = &Xs[(ks * 8 + t4) * 136];
#pragma unroll
            for (int nt = 0; nt < 16; nt++)
                mma8(acc[nt], a0, a1, a2, a3, bp[nt * 8 + g], bp[544 + nt * 8 + g]);
        }
        __syncthreads();
    }
    float* pb = &g_latP[(size_t)blockIdx.x * HYP * HID];
#pragma unroll
    for (int nt = 0; nt < 16; nt++) {
        int cn = nt * 8 + t4 * 2;
        *(float2*)&pb[(h0 + g) * HID + cn]     = make_float2(acc[nt][0], acc[nt][1]);
        *(float2*)&pb[(h0 + g + 8) * HID + cn] = make_float2(acc[nt][2], acc[nt][3]);
    }
}

__global__ void k_latred() {
    int i = blockIdx.x * blockDim.x + threadIdx.x;
    if (i < HYP * HID) {
        float s = 0.f;
        for (int b = 0; b < LATB; b++) s += g_latP[(size_t)b * HYP * HID + i];
        g_lat[i] = s;
    }
}

// ---------------- final = acc/4 + 0.1*normalize(Hm @ lat)  (pipelined) ----------------
__global__ __launch_bounds__(256) void k_final(float* __restrict__ outF) {
    __shared__ uint32_t As[128 * 20];
    __shared__ uint32_t Bs[16 * 136];
    int t = threadIdx.x, lane = t & 31, wid = t >> 5;
    int g = lane >> 2, t4 = lane & 3;
    int r0 = blockIdx.x * 128, m0 = wid * 16;
    float acc[16][4];
#pragma unroll
    for (int n = 0; n < 16; n++) { acc[n][0] = acc[n][1] = acc[n][2] = acc[n][3] = 0.f; }

    int arow = t >> 2, ac = (t & 3) * 4;
    int ga0 = min(r0 + arow, N_NODES - 1), ga1 = min(r0 + arow + 64, N_NODES - 1);
    int brow = t >> 5, bc = (t & 31) * 4;

    float4 ra0 = *(const float4*)(g_Hm + (size_t)ga0 * HYP + ac);
    float4 ra1 = *(const float4*)(g_Hm + (size_t)ga1 * HYP + ac);
    float4 rb0 = *(const float4*)(g_lat + brow * HID + bc);
    float4 rb1 = *(const float4*)(g_lat + (brow + 8) * HID + bc);

    for (int c = 0; c < HYP / 16; c++) {
        *(uint4*)&As[arow * 20 + ac]        = tf32c4(ra0);
        *(uint4*)&As[(arow + 64) * 20 + ac] = tf32c4(ra1);
        *(uint4*)&Bs[brow * 136 + bc]       = tf32c4(rb0);
        *(uint4*)&Bs[(brow + 8) * 136 + bc] = tf32c4(rb1);
        __syncthreads();
        if (c + 1 < HYP / 16) {
            int k0 = (c + 1) * 16;
            ra0 = *(const float4*)(g_Hm + (size_t)ga0 * HYP + k0 + ac);
            ra1 = *(const float4*)(g_Hm + (size_t)ga1 * HYP + k0 + ac);
            rb0 = *(const float4*)(g_lat + (k0 + brow) * HID + bc);
            rb1 = *(const float4*)(g_lat + (k0 + brow + 8) * HID + bc);
        }
#pragma unroll
        for (int ks = 0; ks < 2; ks++) {
            int ar = (m0 + g) * 20 + ks * 8 + t4;
            uint32_t a0 = As[ar], a1 = As[ar + 160], a2 = As[ar + 4], a3 = As[ar + 164];
            const uint32_t* bp = &Bs[(ks * 8 + t4) * 136];
#pragma unroll
            for (int nt = 0; nt < 16; nt++)
                mma8(acc[nt], a0, a1, a2, a3, bp[nt * 8 + g], bp[544 + nt * 8 + g]);
        }
        __syncthreads();
    }

    float ssA = 0.f, ssB = 0.f;
#pragma unroll
    for (int nt = 0; nt < 16; nt++) {
        ssA += acc[nt][0] * acc[nt][0] + acc[nt][1] * acc[nt][1];
        ssB += acc[nt][2] * acc[nt][2] + acc[nt][3] * acc[nt][3];
    }
    ssA += __shfl_xor_sync(0xffffffffu, ssA, 1);
    ssA += __shfl_xor_sync(0xffffffffu, ssA, 2);
    ssB += __shfl_xor_sync(0xffffffffu, ssB, 1);
    ssB += __shfl_xor_sync(0xffffffffu, ssB, 2);
    float iA = 0.1f / fmaxf(sqrtf(ssA), 1e-12f);
    float iB = 0.1f / fmaxf(sqrtf(ssB), 1e-12f);
    int rA = r0 + m0 + g, rB = rA + 8;
#pragma unroll
    for (int nt = 0; nt < 16; nt++) {
        int cn = nt * 8 + t4 * 2;
        if (rA < N_NODES) {
            float2 ag = *(const float2*)&g_acc[rA * HID + cn];
            *(float2*)&outF[(size_t)rA * HID + cn] =
                make_float2(ag.x * 0.25f + acc[nt][0] * iA, ag.y * 0.25f + acc[nt][1] * iA);
        }
        if (rB < N_NODES) {
            float2 ag = *(const float2*)&g_acc[rB * HID + cn];
            *(float2*)&outF[(size_t)rB * HID + cn] =
                make_float2(ag.x * 0.25f + acc[nt][2] * iB, ag.y * 0.25f + acc[nt][3] * iB);
        }
    }
}

// ---------------- vis/txt = relu(final @ [wv|wt] + [bv|bt])  (R5 form) ----------------
__global__ __launch_bounds__(256) void k_out(const float* __restrict__ fin,
                                             const float* __restrict__ wv, const float* __restrict__ bv,
                                             const float* __restrict__ wt, const float* __restrict__ bt,
                                             float* __restrict__ vis, float* __restrict__ txt) {
    __shared__ uint32_t As[64 * 20];
    __shared__ uint32_t Bs[16 * 264];
    int t = threadIdx.x, lane = t & 31, wid = t >> 5;
    int g = lane >> 2, t4 = lane & 3;
    int mt = wid & 3, half = wid >> 2;
    int r0 = blockIdx.x * 64, m0 = mt * 16;
    float acc[16][4];
#pragma unroll
    for (int n = 0; n < 16; n++) { acc[n][0] = acc[n][1] = acc[n][2] = acc[n][3] = 0.f; }

    for (int k0 = 0; k0 < HID; k0 += 16) {
        {
            int i = t;
            int row = i >> 2, c4 = (i & 3) * 4;
            int gr = min(r0 + row, N_NODES - 1);
            *(uint4*)&As[row * 20 + c4] =
                tf32c4(*(const float4*)(fin + (size_t)gr * HID + k0 + c4));
        }
        for (int i = t; i < 1024; i += 256) {
            int row = i >> 6, c4 = (i & 63) * 4;
            const float* srcp = (c4 < 128) ? (wv + (k0 + row) * HID + c4)
                                           : (wt + (k0 + row) * HID + (c4 - 128));
            *(uint4*)&Bs[row * 264 + c4] = tf32c4(*(const float4*)srcp);
        }
        __syncthreads();
#pragma unroll
        for (int ks = 0; ks < 2; ks++) {
            int ar = (m0 + g) * 20 + ks * 8 + t4;
            uint32_t a0 = As[ar], a1 = As[ar + 160], a2 = As[ar + 4], a3 = As[ar + 164];
            const uint32_t* bp = &Bs[(ks * 8 + t4) * 264 + half * 128];
#pragma unroll
            for (int nt = 0; nt < 16; nt++)
                mma8(acc[nt], a0, a1, a2, a3, bp[nt * 8 + g], bp[1056 + nt * 8 + g]);
        }
        __syncthreads();
    }

    const float* bias = half ? bt : bv;
    float* o = half ? txt : vis;
    int rA = r0 + m0 + g, rB = rA + 8;
#pragma unroll
    for (int nt = 0; nt < 16; nt++) {
        int cn = nt * 8 + t4 * 2;
        float b0 = bias[cn], b1 = bias[cn + 1];
        if (rA < N_NODES)
            *(float2*)&o[(size_t)rA * HID + cn] =
                make_float2(fmaxf(acc[nt][0] + b0, 0.f), fmaxf(acc[nt][1] + b1, 0.f));
        if (rB < N_NODES)
            *(float2*)&o[(size_t)rB * HID + cn] =
                make_float2(fmaxf(acc[nt][2] + b0, 0.f), fmaxf(acc[nt][3] + b1, 0.f));
    }
}

// ---------------- launcher: two-stream fork/join inside graph capture ----------------
extern "C" void kernel_launch(void* const* d_in, const int* in_sizes, int n_in,
                              void* d_out, int out_size) {
    const float* x       = (const float*)d_in[0];
    const int*   ei      = (const int*)  d_in[1];
    const float* u       = (const float*)d_in[2];
    const float* w_feat  = (const float*)d_in[3];
    const float* b_feat  = (const float*)d_in[4];
    const float* w_hyper = (const float*)d_in[5];
    const float* w_vis   = (const float*)d_in[6];
    const float* b_vis   = (const float*)d_in[7];
    const float* w_txt   = (const float*)d_in[8];
    const float* b_txt   = (const float*)d_in[9];

    float* out  = (float*)d_out;
    float* outF = out;
    float* outV = out + (size_t)N_NODES * HID;
    float* outT = out + (size_t)2 * N_NODES * HID;

    const int* src = ei;
    const int* dst = ei + N_EDGES;

    int nb = (N_NODES + 1023) / 1024;         // 49
    int g128 = (N_NODES + 127) / 128;         // 391
    int g64  = (N_NODES + 63) / 64;           // 782

    // lazy one-time host resources (no device memory allocation)
    static cudaStream_t sB = nullptr;
    static cudaEvent_t evFork = nullptr, evFill = nullptr, evG1 = nullptr, evLat = nullptr;
    if (sB == nullptr) {
        cudaStreamCreateWithFlags(&sB, cudaStreamNonBlocking);
        cudaEventCreateWithFlags(&evFork, cudaEventDisableTiming);
        cudaEventCreateWithFlags(&evFill, cudaEventDisableTiming);
        cudaEventCreateWithFlags(&evG1,   cudaEventDisableTiming);
        cudaEventCreateWithFlags(&evLat,  cudaEventDisableTiming);
    }

    // fork stream B off the (captured) main stream
    cudaEventRecord(evFork, 0);
    cudaStreamWaitEvent(sB, evFork, 0);

    // stream B: CSR setup chain (independent of gemm1)
    k_zero <<<(N_NODES + 255) / 256, 256, 0, sB>>>();
    k_deg  <<<(N_EDGES + 255) / 256, 256, 0, sB>>>(dst);
    k_scan1<<<nb, 1024, 0, sB>>>();
    k_scan2<<<1, 64, 0, sB>>>(nb);
    k_scan3<<<nb, 1024, 0, sB>>>();
    k_fill <<<(N_EDGES + 255) / 256, 256, 0, sB>>>(src, dst);
    cudaEventRecord(evFill, sB);

    // main stream: feature GEMM (concurrent with setup)
    k_gemm1<<<g128, 256>>>(x, w_feat, b_feat);
    cudaEventRecord(evG1, 0);

    // stream B: hyper branch (needs x_emb only) — concurrent with propagation
    cudaStreamWaitEvent(sB, evG1, 0);
    k_hyp<<<g64, 256, 0, sB>>>(w_hyper, u);
    k_lat<<<LATB, 512, 0, sB>>>();
    k_latred<<<(HYP * HID + 1023) / 1024, 1024, 0, sB>>>();
    cudaEventRecord(evLat, sB);

    // main stream: propagation (needs CSR + x_emb)
    cudaStreamWaitEvent(0, evFill, 0);
    k_prop<<<(N_NODES + 3) / 4, 128>>>(0);
    k_prop<<<(N_NODES + 3) / 4, 128>>>(1);
    k_prop<<<(N_NODES + 3) / 4, 128>>>(2);

    // join: final needs g_acc (main) + g_lat/g_Hm (stream B)
    cudaStreamWaitEvent(0, evLat, 0);
    k_final<<<g128, 256>>>(outF);
    k_out  <<<g64, 256>>>(outF, w_vis, b_vis, w_txt, b_txt, outV, outT);
}

// round 16
// speedup vs baseline: 1.6278x; 1.0861x over previous
#include <cuda_runtime.h>
#include <math.h>
#include <stdint.h>

#define N_NODES 50000
#define N_EDGES 600000
#define IN_DIM  384
#define HID     128
#define HYP     256
#define EPSV    1e-10f
#define LATB    143
#define NPB     352          // 143*352 = 50336 >= 50000

// ---------------- scratch ----------------
__device__ float g_xemb[N_NODES * HID];
__device__ float g_curA[N_NODES * HID];
__device__ float g_curB[N_NODES * HID];
__device__ float g_curC[N_NODES * HID];
__device__ float g_Hm  [N_NODES * HYP];
__device__ float g_lat [HYP * HID];
__device__ float g_latP[LATB * HYP * HID];
__device__ float g_dinv[N_NODES];
__device__ int2  g_csr2[N_EDGES];
__device__ int   g_deg [N_NODES];
__device__ int   g_rowptr[N_NODES + 1];
__device__ int   g_fill[N_NODES];
__device__ int   g_part[64];

// ---------------- tf32 mma helpers ----------------
__device__ __forceinline__ uint32_t tf32c(float f) {
    uint32_t r;
    asm("cvt.rna.tf32.f32 %0, %1;" : "=r"(r) : "f"(f));
    return r;
}

__device__ __forceinline__ uint4 tf32c4(float4 v) {
    uint4 r;
    r.x = tf32c(v.x); r.y = tf32c(v.y); r.z = tf32c(v.z); r.w = tf32c(v.w);
    return r;
}

__device__ __forceinline__ void mma8(float* c,
                                     uint32_t a0, uint32_t a1, uint32_t a2, uint32_t a3,
                                     uint32_t b0, uint32_t b1) {
    asm volatile(
        "mma.sync.aligned.m16n8k8.row.col.f32.tf32.tf32.f32 "
        "{%0,%1,%2,%3},{%4,%5,%6,%7},{%8,%9},{%0,%1,%2,%3};"
        : "+f"(c[0]), "+f"(c[1]), "+f"(c[2]), "+f"(c[3])
        : "r"(a0), "r"(a1), "r"(a2), "r"(a3), "r"(b0), "r"(b1));
}

// ---------------- setup kernels ----------------
__global__ void k_zero() {
    int i = blockIdx.x * blockDim.x + threadIdx.x;
    if (i < N_NODES) { g_deg[i] = 0; g_fill[i] = 0; }
}

__global__ void k_deg(const int* __restrict__ dst) {
    int e = blockIdx.x * blockDim.x + threadIdx.x;
    if (e < N_EDGES) atomicAdd(&g_deg[dst[e]], 1);
}

__global__ void k_scan1() {
    __shared__ int sh[1024];
    int i = blockIdx.x * 1024 + threadIdx.x;
    int v = (i < N_NODES) ? g_deg[i] : 0;
    sh[threadIdx.x] = v;
    __syncthreads();
    for (int off = 1; off < 1024; off <<= 1) {
        int t = (threadIdx.x >= off) ? sh[threadIdx.x - off] : 0;
        __syncthreads();
        sh[threadIdx.x] += t;
        __syncthreads();
    }
    if (i < N_NODES) g_rowptr[i] = sh[threadIdx.x] - v;
    if (threadIdx.x == 1023) g_part[blockIdx.x] = sh[1023];
}

__global__ void k_scan2(int nb) {
    __shared__ int sh[64];
    int v = (threadIdx.x < nb) ? g_part[threadIdx.x] : 0;
    sh[threadIdx.x] = v;
    __syncthreads();
    for (int off = 1; off < 64; off <<= 1) {
        int t = (threadIdx.x >= off) ? sh[threadIdx.x - off] : 0;
        __syncthreads();
        sh[threadIdx.x] += t;
        __syncthreads();
    }
    if (threadIdx.x < nb) g_part[threadIdx.x] = sh[threadIdx.x] - v;
}

// scan finalize + dinv fused
__global__ void k_scan3() {
    int i = blockIdx.x * 1024 + threadIdx.x;
    if (i < N_NODES) {
        g_rowptr[i] += g_part[blockIdx.x];
        int d = g_deg[i];
        g_dinv[i] = (d > 0) ? rsqrtf((float)d) : 0.f;
    }
    if (i == 0) g_rowptr[N_NODES] = N_EDGES;
}

__global__ void k_fill(const int* __restrict__ src, const int* __restrict__ dst) {
    int e = blockIdx.x * blockDim.x + threadIdx.x;
    if (e < N_EDGES) {
        int d = dst[e], s = src[e];
        int pos = g_rowptr[d] + atomicAdd(&g_fill[d], 1);
        g_csr2[pos] = make_int2(s, __float_as_int(g_dinv[s] * g_dinv[d]));
    }
}

// ---------------- G1: x_emb = x @ w_feat + b_feat (pipelined) ----------
__global__ __launch_bounds__(256) void k_gemm1(const float* __restrict__ x,
                                               const float* __restrict__ w,
                                               const float* __restrict__ b) {
    __shared__ uint32_t As[128 * 20];
    __shared__ uint32_t Bs[16 * 136];
    int t = threadIdx.x, lane = t & 31, wid = t >> 5;
    int g = lane >> 2, t4 = lane & 3;
    int r0 = blockIdx.x * 128, m0 = wid * 16;
    float acc[16][4];
#pragma unroll
    for (int n = 0; n < 16; n++) { acc[n][0] = acc[n][1] = acc[n][2] = acc[n][3] = 0.f; }

    int arow = t >> 2, ac = (t & 3) * 4;
    int ga0 = min(r0 + arow, N_NODES - 1), ga1 = min(r0 + arow + 64, N_NODES - 1);
    int brow = t >> 5, bc = (t & 31) * 4;

    float4 ra0 = *(const float4*)(x + (size_t)ga0 * IN_DIM + ac);
    float4 ra1 = *(const float4*)(x + (size_t)ga1 * IN_DIM + ac);
    float4 rb0 = *(const float4*)(w + brow * HID + bc);
    float4 rb1 = *(const float4*)(w + (brow + 8) * HID + bc);

    for (int c = 0; c < IN_DIM / 16; c++) {
        *(uint4*)&As[arow * 20 + ac]        = tf32c4(ra0);
        *(uint4*)&As[(arow + 64) * 20 + ac] = tf32c4(ra1);
        *(uint4*)&Bs[brow * 136 + bc]       = tf32c4(rb0);
        *(uint4*)&Bs[(brow + 8) * 136 + bc] = tf32c4(rb1);
        __syncthreads();
        if (c + 1 < IN_DIM / 16) {
            int k0 = (c + 1) * 16;
            ra0 = *(const float4*)(x + (size_t)ga0 * IN_DIM + k0 + ac);
            ra1 = *(const float4*)(x + (size_t)ga1 * IN_DIM + k0 + ac);
            rb0 = *(const float4*)(w + (k0 + brow) * HID + bc);
            rb1 = *(const float4*)(w + (k0 + brow + 8) * HID + bc);
        }
#pragma unroll
        for (int ks = 0; ks < 2; ks++) {
            int ar = (m0 + g) * 20 + ks * 8 + t4;
            uint32_t a0 = As[ar], a1 = As[ar + 160], a2 = As[ar + 4], a3 = As[ar + 164];
            const uint32_t* bp = &Bs[(ks * 8 + t4) * 136];
#pragma unroll
            for (int nt = 0; nt < 16; nt++)
                mma8(acc[nt], a0, a1, a2, a3, bp[nt * 8 + g], bp[544 + nt * 8 + g]);
        }
        __syncthreads();
    }
    int rA = r0 + m0 + g, rB = rA + 8;
#pragma unroll
    for (int nt = 0; nt < 16; nt++) {
        int cn = nt * 8 + t4 * 2;
        float b0 = b[cn], b1 = b[cn + 1];
        if (rA < N_NODES)
            *(float2*)&g_xemb[rA * HID + cn] = make_float2(acc[nt][0] + b0, acc[nt][1] + b1);
        if (rB < N_NODES)
            *(float2*)&g_xemb[rB * HID + cn] = make_float2(acc[nt][2] + b0, acc[nt][3] + b1);
    }
}

// ---------------- propagation: warp per node, float4, no acc RMW ----------------
__global__ __launch_bounds__(128) void k_prop(int step) {
    const float* cur = (step == 0) ? g_xemb : ((step == 1) ? g_curA : g_curB);
    float*       nxt = (step == 0) ? g_curA : ((step == 1) ? g_curB : g_curC);
    int d = blockIdx.x * 4 + (threadIdx.x >> 5);
    if (d >= N_NODES) return;
    int lane = threadIdx.x & 31;
    int s0 = g_rowptr[d], s1 = g_rowptr[d + 1];
    float4 sum = make_float4(0.f, 0.f, 0.f, 0.f);
    for (int j = s0; j < s1; j++) {
        int2 e = g_csr2[j];
        float v = __int_as_float(e.y);
        float4 c4v = *(const float4*)&cur[(size_t)e.x * HID + lane * 4];
        sum.x = fmaf(c4v.x, v, sum.x);
        sum.y = fmaf(c4v.y, v, sum.y);
        sum.z = fmaf(c4v.z, v, sum.z);
        sum.w = fmaf(c4v.w, v, sum.w);
    }
    *(float4*)&nxt[(size_t)d * HID + lane * 4] = sum;
}

// ------- Hm = softmax((x_emb @ w_hyper + gumbel)*2); M=64, N-split, pipelined -----
__global__ __launch_bounds__(256) void k_hyp(const float* __restrict__ wh_,
                                             const float* __restrict__ u) {
    __shared__ uint32_t As[64 * 20];
    __shared__ uint32_t Bs[16 * 264];
    __shared__ float redM[4][8][2][2];   // [wq][g][AB][wh]
    __shared__ float redS[4][8][2][2];
    int t = threadIdx.x, lane = t & 31, wid = t >> 5;
    int g = lane >> 2, t4 = lane & 3;
    int wq = wid & 3, wh = wid >> 2;     // row-group / column-half
    int r0 = blockIdx.x * 64, m0 = wq * 16;
    float acc[16][4];
#pragma unroll
    for (int n = 0; n < 16; n++) { acc[n][0] = acc[n][1] = acc[n][2] = acc[n][3] = 0.f; }

    int arow = t >> 2, ac = (t & 3) * 4;
    int ga0 = min(r0 + arow, N_NODES - 1);
    int brow = t >> 6, bc = (t & 63) * 4;

    float4 ra = *(const float4*)(g_xemb + (size_t)ga0 * HID + ac);
    float4 rb[4];
#pragma unroll
    for (int l = 0; l < 4; l++)
        rb[l] = *(const float4*)(wh_ + (brow + l * 4) * HYP + bc);

    for (int c = 0; c < HID / 16; c++) {
        *(uint4*)&As[arow * 20 + ac] = tf32c4(ra);
#pragma unroll
        for (int l = 0; l < 4; l++)
            *(uint4*)&Bs[(brow + l * 4) * 264 + bc] = tf32c4(rb[l]);
        __syncthreads();
        if (c + 1 < HID / 16) {
            int k0 = (c + 1) * 16;
            ra = *(const float4*)(g_xemb + (size_t)ga0 * HID + k0 + ac);
#pragma unroll
            for (int l = 0; l < 4; l++)
                rb[l] = *(const float4*)(wh_ + (k0 + brow + l * 4) * HYP + bc);
        }
#pragma unroll
        for (int ks = 0; ks < 2; ks++) {
            int ar = (m0 + g) * 20 + ks * 8 + t4;
            uint32_t a0 = As[ar], a1 = As[ar + 160], a2 = As[ar + 4], a3 = As[ar + 164];
            const uint32_t* bp = &Bs[(ks * 8 + t4) * 264 + wh * 128];
#pragma unroll
            for (int nt = 0; nt < 16; nt++)
                mma8(acc[nt], a0, a1, a2, a3, bp[nt * 8 + g], bp[1056 + nt * 8 + g]);
        }
        __syncthreads();
    }

    int rA = r0 + m0 + g, rB = rA + 8;
    int uA = min(rA, N_NODES - 1), uB = min(rB, N_NODES - 1);
    int cb = wh * 128;
    float mA = -1e30f, mB = -1e30f;
#pragma unroll
    for (int nt = 0; nt < 16; nt++) {
        int cn = cb + nt * 8 + t4 * 2;
        float2 ua = *(const float2*)(u + (size_t)uA * HYP + cn);
        float2 ub = *(const float2*)(u + (size_t)uB * HYP + cn);
        acc[nt][0] = (acc[nt][0] - __logf(-logf(ua.x + EPSV) + EPSV)) * 2.f;
        acc[nt][1] = (acc[nt][1] - __logf(-logf(ua.y + EPSV) + EPSV)) * 2.f;
        acc[nt][2] = (acc[nt][2] - __logf(-logf(ub.x + EPSV) + EPSV)) * 2.f;
        acc[nt][3] = (acc[nt][3] - __logf(-logf(ub.y + EPSV) + EPSV)) * 2.f;
        mA = fmaxf(mA, fmaxf(acc[nt][0], acc[nt][1]));
        mB = fmaxf(mB, fmaxf(acc[nt][2], acc[nt][3]));
    }
    mA = fmaxf(mA, __shfl_xor_sync(0xffffffffu, mA, 1));
    mA = fmaxf(mA, __shfl_xor_sync(0xffffffffu, mA, 2));
    mB = fmaxf(mB, __shfl_xor_sync(0xffffffffu, mB, 1));
    mB = fmaxf(mB, __shfl_xor_sync(0xffffffffu, mB, 2));
    if (t4 == 0) { redM[wq][g][0][wh] = mA; redM[wq][g][1][wh] = mB; }
    __syncthreads();
    mA = fmaxf(redM[wq][g][0][0], redM[wq][g][0][1]);
    mB = fmaxf(redM[wq][g][1][0], redM[wq][g][1][1]);

    float sA = 0.f, sB = 0.f;
#pragma unroll
    for (int nt = 0; nt < 16; nt++) {
        acc[nt][0] = __expf(acc[nt][0] - mA);
        acc[nt][1] = __expf(acc[nt][1] - mA);
        acc[nt][2] = __expf(acc[nt][2] - mB);
        acc[nt][3] = __expf(acc[nt][3] - mB);
        sA += acc[nt][0] + acc[nt][1];
        sB += acc[nt][2] + acc[nt][3];
    }
    sA += __shfl_xor_sync(0xffffffffu, sA, 1);
    sA += __shfl_xor_sync(0xffffffffu, sA, 2);
    sB += __shfl_xor_sync(0xffffffffu, sB, 1);
    sB += __shfl_xor_sync(0xffffffffu, sB, 2);
    if (t4 == 0) { redS[wq][g][0][wh] = sA; redS[wq][g][1][wh] = sB; }
    __syncthreads();
    float iA = 1.f / (redS[wq][g][0][0] + redS[wq][g][0][1]);
    float iB = 1.f / (redS[wq][g][1][0] + redS[wq][g][1][1]);

#pragma unroll
    for (int nt = 0; nt < 16; nt++) {
        int cn = cb + nt * 8 + t4 * 2;
        if (rA < N_NODES)
            *(float2*)&g_Hm[(size_t)rA * HYP + cn] = make_float2(acc[nt][0] * iA, acc[nt][1] * iA);
        if (rB < N_NODES)
            *(float2*)&g_Hm[(size_t)rB * HYP + cn] = make_float2(acc[nt][2] * iB, acc[nt][3] * iB);
    }
}

// ---------------- lat partials: latP[b] = Hm[rows_b]^T @ xemb[rows_b] (pipelined) -----
__global__ __launch_bounds__(512) void k_lat() {
    __shared__ uint32_t Hs[16 * 264];
    __shared__ uint32_t Xs[16 * 136];
    int t = threadIdx.x, lane = t & 31, wid = t >> 5;
    int g = lane >> 2, t4 = lane & 3;
    int h0 = wid * 16;
    int base = blockIdx.x * NPB;
    float acc[16][4];
#pragma unroll
    for (int n = 0; n < 16; n++) { acc[n][0] = acc[n][1] = acc[n][2] = acc[n][3] = 0.f; }

    int hrow = t >> 6, hc = (t & 63) * 4;
    int xrow = t >> 5, xc = (t & 31) * 4;

    float4 rh0, rh1, rx;
    {
        int n0 = base + hrow, n1 = base + hrow + 8, n2 = base + xrow;
        rh0 = (n0 < N_NODES) ? *(const float4*)&g_Hm[(size_t)n0 * HYP + hc] : make_float4(0,0,0,0);
        rh1 = (n1 < N_NODES) ? *(const float4*)&g_Hm[(size_t)n1 * HYP + hc] : make_float4(0,0,0,0);
        rx  = (n2 < N_NODES) ? *(const float4*)&g_xemb[(size_t)n2 * HID + xc] : make_float4(0,0,0,0);
    }

    for (int c = 0; c < NPB; c += 16) {
        *(uint4*)&Hs[hrow * 264 + hc]       = tf32c4(rh0);
        *(uint4*)&Hs[(hrow + 8) * 264 + hc] = tf32c4(rh1);
        *(uint4*)&Xs[xrow * 136 + xc]       = tf32c4(rx);
        __syncthreads();
        if (c + 16 < NPB) {
            int n0 = base + c + 16 + hrow, n1 = n0 + 8, n2 = base + c + 16 + xrow;
            rh0 = (n0 < N_NODES) ? *(const float4*)&g_Hm[(size_t)n0 * HYP + hc] : make_float4(0,0,0,0);
            rh1 = (n1 < N_NODES) ? *(const float4*)&g_Hm[(size_t)n1 * HYP + hc] : make_float4(0,0,0,0);
            rx  = (n2 < N_NODES) ? *(const float4*)&g_xemb[(size_t)n2 * HID + xc] : make_float4(0,0,0,0);
        }
#pragma unroll
        for (int ks = 0; ks < 2; ks++) {
            const uint32_t* hp  = &Hs[(ks * 8 + t4) * 264];
            const uint32_t* hp4 = hp + 4 * 264;
            uint32_t a0 = hp[h0 + g],  a1 = hp[h0 + g + 8];
            uint32_t a2 = hp4[h0 + g], a3 = hp4[h0 + g + 8];
            const uint32_t* bp = &Xs[(ks * 8 + t4) * 136];
#pragma unroll
            for (int nt = 0; nt < 16; nt++)
                mma8(acc[nt], a0, a1, a2, a3, bp[nt * 8 + g], bp[544 + nt * 8 + g]);
        }
        __syncthreads();
    }
    float* pb = &g_latP[(size_t)blockIdx.x * HYP * HID];
#pragma unroll
    for (int nt = 0; nt < 16; nt++) {
        int cn = nt * 8 + t4 * 2;
        *(float2*)&pb[(h0 + g) * HID + cn]     = make_float2(acc[nt][0], acc[nt][1]);
        *(float2*)&pb[(h0 + g + 8) * HID + cn] = make_float2(acc[nt][2], acc[nt][3]);
    }
}

__global__ void k_latred() {
    int i = blockIdx.x * blockDim.x + threadIdx.x;
    if (i < HYP * HID) {
        float s = 0.f;
        for (int b = 0; b < LATB; b++) s += g_latP[(size_t)b * HYP * HID + i];
        g_lat[i] = s;
    }
}

// ------ final = (xemb+c1+c2+c3)/4 + 0.1*normalize(Hm @ lat)  (pipelined) ------
__global__ __launch_bounds__(256) void k_final(float* __restrict__ outF) {
    __shared__ uint32_t As[128 * 20];
    __shared__ uint32_t Bs[16 * 136];
    int t = threadIdx.x, lane = t & 31, wid = t >> 5;
    int g = lane >> 2, t4 = lane & 3;
    int r0 = blockIdx.x * 128, m0 = wid * 16;
    float acc[16][4];
#pragma unroll
    for (int n = 0; n < 16; n++) { acc[n][0] = acc[n][1] = acc[n][2] = acc[n][3] = 0.f; }

    int arow = t >> 2, ac = (t & 3) * 4;
    int ga0 = min(r0 + arow, N_NODES - 1), ga1 = min(r0 + arow + 64, N_NODES - 1);
    int brow = t >> 5, bc = (t & 31) * 4;

    float4 ra0 = *(const float4*)(g_Hm + (size_t)ga0 * HYP + ac);
    float4 ra1 = *(const float4*)(g_Hm + (size_t)ga1 * HYP + ac);
    float4 rb0 = *(const float4*)(g_lat + brow * HID + bc);
    float4 rb1 = *(const float4*)(g_lat + (brow + 8) * HID + bc);

    for (int c = 0; c < HYP / 16; c++) {
        *(uint4*)&As[arow * 20 + ac]        = tf32c4(ra0);
        *(uint4*)&As[(arow + 64) * 20 + ac] = tf32c4(ra1);
        *(uint4*)&Bs[brow * 136 + bc]       = tf32c4(rb0);
        *(uint4*)&Bs[(brow + 8) * 136 + bc] = tf32c4(rb1);
        __syncthreads();
        if (c + 1 < HYP / 16) {
            int k0 = (c + 1) * 16;
            ra0 = *(const float4*)(g_Hm + (size_t)ga0 * HYP + k0 + ac);
            ra1 = *(const float4*)(g_Hm + (size_t)ga1 * HYP + k0 + ac);
            rb0 = *(const float4*)(g_lat + (k0 + brow) * HID + bc);
            rb1 = *(const float4*)(g_lat + (k0 + brow + 8) * HID + bc);
        }
#pragma unroll
        for (int ks = 0; ks < 2; ks++) {
            int ar = (m0 + g) * 20 + ks * 8 + t4;
            uint32_t a0 = As[ar], a1 = As[ar + 160], a2 = As[ar + 4], a3 = As[ar + 164];
            const uint32_t* bp = &Bs[(ks * 8 + t4) * 136];
#pragma unroll
            for (int nt = 0; nt < 16; nt++)
                mma8(acc[nt], a0, a1, a2, a3, bp[nt * 8 + g], bp[544 + nt * 8 + g]);
        }
        __syncthreads();
    }

    float ssA = 0.f, ssB = 0.f;
#pragma unroll
    for (int nt = 0; nt < 16; nt++) {
        ssA += acc[nt][0] * acc[nt][0] + acc[nt][1] * acc[nt][1];
        ssB += acc[nt][2] * acc[nt][2] + acc[nt][3] * acc[nt][3];
    }
    ssA += __shfl_xor_sync(0xffffffffu, ssA, 1);
    ssA += __shfl_xor_sync(0xffffffffu, ssA, 2);
    ssB += __shfl_xor_sync(0xffffffffu, ssB, 1);
    ssB += __shfl_xor_sync(0xffffffffu, ssB, 2);
    float iA = 0.1f / fmaxf(sqrtf(ssA), 1e-12f);
    float iB = 0.1f / fmaxf(sqrtf(ssB), 1e-12f);
    int rA = r0 + m0 + g, rB = rA + 8;
#pragma unroll
    for (int nt = 0; nt < 16; nt++) {
        int cn = nt * 8 + t4 * 2;
        if (rA < N_NODES) {
            size_t o = (size_t)rA * HID + cn;
            float2 e0 = *(const float2*)&g_xemb[o];
            float2 c1 = *(const float2*)&g_curA[o];
            float2 c2 = *(const float2*)&g_curB[o];
            float2 c3 = *(const float2*)&g_curC[o];
            float lx = ((e0.x + c1.x) + c2.x) + c3.x;
            float ly = ((e0.y + c1.y) + c2.y) + c3.y;
            *(float2*)&outF[o] =
                make_float2(lx * 0.25f + acc[nt][0] * iA, ly * 0.25f + acc[nt][1] * iA);
        }
        if (rB < N_NODES) {
            size_t o = (size_t)rB * HID + cn;
            float2 e0 = *(const float2*)&g_xemb[o];
            float2 c1 = *(const float2*)&g_curA[o];
            float2 c2 = *(const float2*)&g_curB[o];
            float2 c3 = *(const float2*)&g_curC[o];
            float lx = ((e0.x + c1.x) + c2.x) + c3.x;
            float ly = ((e0.y + c1.y) + c2.y) + c3.y;
            *(float2*)&outF[o] =
                make_float2(lx * 0.25f + acc[nt][2] * iB, ly * 0.25f + acc[nt][3] * iB);
        }
    }
}

// ---------------- vis/txt = relu(final @ [wv|wt] + [bv|bt]) ----------------
__global__ __launch_bounds__(256) void k_out(const float* __restrict__ fin,
                                             const float* __restrict__ wv, const float* __restrict__ bv,
                                             const float* __restrict__ wt, const float* __restrict__ bt,
                                             float* __restrict__ vis, float* __restrict__ txt) {
    __shared__ uint32_t As[64 * 20];
    __shared__ uint32_t Bs[16 * 264];
    int t = threadIdx.x, lane = t & 31, wid = t >> 5;
    int g = lane >> 2, t4 = lane & 3;
    int mt = wid & 3, half = wid >> 2;
    int r0 = blockIdx.x * 64, m0 = mt * 16;
    float acc[16][4];
#pragma unroll
    for (int n = 0; n < 16; n++) { acc[n][0] = acc[n][1] = acc[n][2] = acc[n][3] = 0.f; }

    for (int k0 = 0; k0 < HID; k0 += 16) {
        {
            int i = t;
            int row = i >> 2, c4 = (i & 3) * 4;
            int gr = min(r0 + row, N_NODES - 1);
            *(uint4*)&As[row * 20 + c4] =
                tf32c4(*(const float4*)(fin + (size_t)gr * HID + k0 + c4));
        }
        for (int i = t; i < 1024; i += 256) {
            int row = i >> 6, c4 = (i & 63) * 4;
            const float* srcp = (c4 < 128) ? (wv + (k0 + row) * HID + c4)
                                           : (wt + (k0 + row) * HID + (c4 - 128));
            *(uint4*)&Bs[row * 264 + c4] = tf32c4(*(const float4*)srcp);
        }
        __syncthreads();
#pragma unroll
        for (int ks = 0; ks < 2; ks++) {
            int ar = (m0 + g) * 20 + ks * 8 + t4;
            uint32_t a0 = As[ar], a1 = As[ar + 160], a2 = As[ar + 4], a3 = As[ar + 164];
            const uint32_t* bp = &Bs[(ks * 8 + t4) * 264 + half * 128];
#pragma unroll
            for (int nt = 0; nt < 16; nt++)
                mma8(acc[nt], a0, a1, a2, a3, bp[nt * 8 + g], bp[1056 + nt * 8 + g]);
        }
        __syncthreads();
    }

    const float* bias = half ? bt : bv;
    float* o = half ? txt : vis;
    int rA = r0 + m0 + g, rB = rA + 8;
#pragma unroll
    for (int nt = 0; nt < 16; nt++) {
        int cn = nt * 8 + t4 * 2;
        float b0 = bias[cn], b1 = bias[cn + 1];
        if (rA < N_NODES)
            *(float2*)&o[(size_t)rA * HID + cn] =
                make_float2(fmaxf(acc[nt][0] + b0, 0.f), fmaxf(acc[nt][1] + b1, 0.f));
        if (rB < N_NODES)
            *(float2*)&o[(size_t)rB * HID + cn] =
                make_float2(fmaxf(acc[nt][2] + b0, 0.f), fmaxf(acc[nt][3] + b1, 0.f));
    }
}

// ---------------- launcher: two-stream fork/join inside graph capture ----------------
extern "C" void kernel_launch(void* const* d_in, const int* in_sizes, int n_in,
                              void* d_out, int out_size) {
    const float* x       = (const float*)d_in[0];
    const int*   ei      = (const int*)  d_in[1];
    const float* u       = (const float*)d_in[2];
    const float* w_feat  = (const float*)d_in[3];
    const float* b_feat  = (const float*)d_in[4];
    const float* w_hyper = (const float*)d_in[5];
    const float* w_vis   = (const float*)d_in[6];
    const float* b_vis   = (const float*)d_in[7];
    const float* w_txt   = (const float*)d_in[8];
    const float* b_txt   = (const float*)d_in[9];

    float* out  = (float*)d_out;
    float* outF = out;
    float* outV = out + (size_t)N_NODES * HID;
    float* outT = out + (size_t)2 * N_NODES * HID;

    const int* src = ei;
    const int* dst = ei + N_EDGES;

    int nb = (N_NODES + 1023) / 1024;         // 49
    int g128 = (N_NODES + 127) / 128;         // 391
    int g64  = (N_NODES + 63) / 64;           // 782

    // lazy one-time host resources (no device memory allocation)
    static cudaStream_t sB = nullptr;
    static cudaEvent_t evFork = nullptr, evFill = nullptr, evG1 = nullptr, evLat = nullptr;
    if (sB == nullptr) {
        cudaStreamCreateWithFlags(&sB, cudaStreamNonBlocking);
        cudaEventCreateWithFlags(&evFork, cudaEventDisableTiming);
        cudaEventCreateWithFlags(&evFill, cudaEventDisableTiming);
        cudaEventCreateWithFlags(&evG1,   cudaEventDisableTiming);
        cudaEventCreateWithFlags(&evLat,  cudaEventDisableTiming);
    }

    // fork stream B off the (captured) main stream
    cudaEventRecord(evFork, 0);
    cudaStreamWaitEvent(sB, evFork, 0);

    // stream B: CSR setup chain (independent of gemm1)
    k_zero <<<(N_NODES + 255) / 256, 256, 0, sB>>>();
    k_deg  <<<(N_EDGES + 255) / 256, 256, 0, sB>>>(dst);
    k_scan1<<<nb, 1024, 0, sB>>>();
    k_scan2<<<1, 64, 0, sB>>>(nb);
    k_scan3<<<nb, 1024, 0, sB>>>();
    k_fill <<<(N_EDGES + 255) / 256, 256, 0, sB>>>(src, dst);
    cudaEventRecord(evFill, sB);

    // main stream: feature GEMM (concurrent with setup)
    k_gemm1<<<g128, 256>>>(x, w_feat, b_feat);
    cudaEventRecord(evG1, 0);

    // stream B: hyper branch (needs x_emb only) — concurrent with propagation
    cudaStreamWaitEvent(sB, evG1, 0);
    k_hyp<<<g64, 256, 0, sB>>>(w_hyper, u);
    k_lat<<<LATB, 512, 0, sB>>>();
    k_latred<<<(HYP * HID + 1023) / 1024, 1024, 0, sB>>>();
    cudaEventRecord(evLat, sB);

    // main stream: propagation (needs CSR + x_emb)
    cudaStreamWaitEvent(0, evFill, 0);
    k_prop<<<(N_NODES + 3) / 4, 128>>>(0);
    k_prop<<<(N_NODES + 3) / 4, 128>>>(1);
    k_prop<<<(N_NODES + 3) / 4, 128>>>(2);

    // join: final needs layer outputs (main) + g_lat/g_Hm (stream B)
    cudaStreamWaitEvent(0, evLat, 0);
    k_final<<<g128, 256>>>(outF);
    k_out  <<<g64, 256>>>(outF, w_vis, b_vis, w_txt, b_txt, outV, outT);
}

// round 17
// speedup vs baseline: 1.6661x; 1.0235x over previous
#include <cuda_runtime.h>
#include <math.h>
#include <stdint.h>

#define N_NODES 50000
#define N_EDGES 600000
#define IN_DIM  384
#define HID     128
#define HYP     256
#define EPSV    1e-10f
#define LATB    143
#define NPB     352          // 143*352 = 50336 >= 50000

// ---------------- scratch ----------------
__device__ float g_xemb[N_NODES * HID];
__device__ float g_curA[N_NODES * HID];
__device__ float g_curB[N_NODES * HID];
__device__ float g_curC[N_NODES * HID];
__device__ float g_Hm  [N_NODES * HYP];
__device__ float g_lat [HYP * HID];
__device__ float g_latP[LATB * HYP * HID];
__device__ float g_dinv[N_NODES];
__device__ int2  g_csr2[N_EDGES];
__device__ int   g_deg [N_NODES];
__device__ int   g_rowptr[N_NODES + 1];
__device__ int   g_fill[N_NODES];
__device__ int   g_part[64];

// ---------------- tf32 mma helpers ----------------
__device__ __forceinline__ uint32_t tf32c(float f) {
    uint32_t r;
    asm("cvt.rna.tf32.f32 %0, %1;" : "=r"(r) : "f"(f));
    return r;
}

// interleave-pack (k, k+4) float4 pair into 8 tf32 words: [f0.x,f1.x,f0.y,f1.y,f0.z,f1.z,f0.w,f1.w]
__device__ __forceinline__ void packpair(uint32_t* dst, float4 f0, float4 f1) {
    uint4 u0, u1;
    u0.x = tf32c(f0.x); u0.y = tf32c(f1.x); u0.z = tf32c(f0.y); u0.w = tf32c(f1.y);
    u1.x = tf32c(f0.z); u1.y = tf32c(f1.z); u1.z = tf32c(f0.w); u1.w = tf32c(f1.w);
    *(uint4*)dst = u0;
    *(uint4*)(dst + 4) = u1;
}

__device__ __forceinline__ void mma8(float* c,
                                     uint32_t a0, uint32_t a1, uint32_t a2, uint32_t a3,
                                     uint32_t b0, uint32_t b1) {
    asm volatile(
        "mma.sync.aligned.m16n8k8.row.col.f32.tf32.tf32.f32 "
        "{%0,%1,%2,%3},{%4,%5,%6,%7},{%8,%9},{%0,%1,%2,%3};"
        : "+f"(c[0]), "+f"(c[1]), "+f"(c[2]), "+f"(c[3])
        : "r"(a0), "r"(a1), "r"(a2), "r"(a3), "r"(b0), "r"(b1));
}

// ---------------- setup kernels ----------------
__global__ void k_zero() {
    int i = blockIdx.x * blockDim.x + threadIdx.x;
    if (i < N_NODES) { g_deg[i] = 0; g_fill[i] = 0; }
}

__global__ void k_deg(const int* __restrict__ dst) {
    int e = blockIdx.x * blockDim.x + threadIdx.x;
    if (e < N_EDGES) atomicAdd(&g_deg[dst[e]], 1);
}

__global__ void k_scan1() {
    __shared__ int sh[1024];
    int i = blockIdx.x * 1024 + threadIdx.x;
    int v = (i < N_NODES) ? g_deg[i] : 0;
    sh[threadIdx.x] = v;
    __syncthreads();
    for (int off = 1; off < 1024; off <<= 1) {
        int t = (threadIdx.x >= off) ? sh[threadIdx.x - off] : 0;
        __syncthreads();
        sh[threadIdx.x] += t;
        __syncthreads();
    }
    if (i < N_NODES) g_rowptr[i] = sh[threadIdx.x] - v;
    if (threadIdx.x == 1023) g_part[blockIdx.x] = sh[1023];
}

__global__ void k_scan2(int nb) {
    __shared__ int sh[64];
    int v = (threadIdx.x < nb) ? g_part[threadIdx.x] : 0;
    sh[threadIdx.x] = v;
    __syncthreads();
    for (int off = 1; off < 64; off <<= 1) {
        int t = (threadIdx.x >= off) ? sh[threadIdx.x - off] : 0;
        __syncthreads();
        sh[threadIdx.x] += t;
        __syncthreads();
    }
    if (threadIdx.x < nb) g_part[threadIdx.x] = sh[threadIdx.x] - v;
}

__global__ void k_scan3() {
    int i = blockIdx.x * 1024 + threadIdx.x;
    if (i < N_NODES) {
        g_rowptr[i] += g_part[blockIdx.x];
        int d = g_deg[i];
        g_dinv[i] = (d > 0) ? rsqrtf((float)d) : 0.f;
    }
    if (i == 0) g_rowptr[N_NODES] = N_EDGES;
}

__global__ void k_fill(const int* __restrict__ src, const int* __restrict__ dst) {
    int e = blockIdx.x * blockDim.x + threadIdx.x;
    if (e < N_EDGES) {
        int d = dst[e], s = src[e];
        int pos = g_rowptr[d] + atomicAdd(&g_fill[d], 1);
        g_csr2[pos] = make_int2(s, __float_as_int(g_dinv[s] * g_dinv[d]));
    }
}

// ---------------- G1: x_emb = x @ w_feat + b_feat (pipelined, pair-packed) ----------
__global__ __launch_bounds__(256) void k_gemm1(const float* __restrict__ x,
                                               const float* __restrict__ w,
                                               const float* __restrict__ b) {
    __shared__ uint32_t As[128 * 20];     // k-interleaved within each row
    __shared__ uint32_t Bs[8 * 264];      // pair-packed
    int t = threadIdx.x, lane = t & 31, wid = t >> 5;
    int g = lane >> 2, t4 = lane & 3;
    int r0 = blockIdx.x * 128, m0 = wid * 16;
    float acc[16][4];
#pragma unroll
    for (int n = 0; n < 16; n++) { acc[n][0] = acc[n][1] = acc[n][2] = acc[n][3] = 0.f; }

    int arow = t >> 1, ak = (t & 1) * 8;
    int ga = min(r0 + arow, N_NODES - 1);
    int bpr = t >> 5, bn = (t & 31) * 4;
    int bk = (bpr >> 2) * 8 + (bpr & 3);

    float4 fa0 = *(const float4*)(x + (size_t)ga * IN_DIM + ak);
    float4 fa1 = *(const float4*)(x + (size_t)ga * IN_DIM + ak + 4);
    float4 fb0 = *(const float4*)(w + bk * HID + bn);
    float4 fb1 = *(const float4*)(w + (bk + 4) * HID + bn);

    for (int c = 0; c < IN_DIM / 16; c++) {
        packpair(&As[arow * 20 + ak], fa0, fa1);
        packpair(&Bs[bpr * 264 + bn * 2], fb0, fb1);
        __syncthreads();
        if (c + 1 < IN_DIM / 16) {
            int k0 = (c + 1) * 16;
            fa0 = *(const float4*)(x + (size_t)ga * IN_DIM + k0 + ak);
            fa1 = *(const float4*)(x + (size_t)ga * IN_DIM + k0 + ak + 4);
            fb0 = *(const float4*)(w + (k0 + bk) * HID + bn);
            fb1 = *(const float4*)(w + (k0 + bk + 4) * HID + bn);
        }
#pragma unroll
        for (int ks = 0; ks < 2; ks++) {
            int ar = (m0 + g) * 20 + ks * 8 + t4 * 2;
            uint2 av0 = *(const uint2*)&As[ar];        // (m, klo), (m, khi)
            uint2 av1 = *(const uint2*)&As[ar + 160];  // (m+8, klo), (m+8, khi)
            const uint32_t* bp = &Bs[(ks * 4 + t4) * 264];
#pragma unroll
            for (int nt = 0; nt < 16; nt++) {
                uint2 bv = *(const uint2*)&bp[(nt * 8 + g) * 2];
                mma8(acc[nt], av0.x, av1.x, av0.y, av1.y, bv.x, bv.y);
            }
        }
        __syncthreads();
    }
    int rA = r0 + m0 + g, rB = rA + 8;
#pragma unroll
    for (int nt = 0; nt < 16; nt++) {
        int cn = nt * 8 + t4 * 2;
        float b0 = b[cn], b1 = b[cn + 1];
        if (rA < N_NODES)
            *(float2*)&g_xemb[rA * HID + cn] = make_float2(acc[nt][0] + b0, acc[nt][1] + b1);
        if (rB < N_NODES)
            *(float2*)&g_xemb[rB * HID + cn] = make_float2(acc[nt][2] + b0, acc[nt][3] + b1);
    }
}

// ---------------- propagation: warp per node, float4, no acc RMW ----------------
__global__ __launch_bounds__(128) void k_prop(int step) {
    const float* cur = (step == 0) ? g_xemb : ((step == 1) ? g_curA : g_curB);
    float*       nxt = (step == 0) ? g_curA : ((step == 1) ? g_curB : g_curC);
    int d = blockIdx.x * 4 + (threadIdx.x >> 5);
    if (d >= N_NODES) return;
    int lane = threadIdx.x & 31;
    int s0 = g_rowptr[d], s1 = g_rowptr[d + 1];
    float4 sum = make_float4(0.f, 0.f, 0.f, 0.f);
    for (int j = s0; j < s1; j++) {
        int2 e = g_csr2[j];
        float v = __int_as_float(e.y);
        float4 c4v = *(const float4*)&cur[(size_t)e.x * HID + lane * 4];
        sum.x = fmaf(c4v.x, v, sum.x);
        sum.y = fmaf(c4v.y, v, sum.y);
        sum.z = fmaf(c4v.z, v, sum.z);
        sum.w = fmaf(c4v.w, v, sum.w);
    }
    *(float4*)&nxt[(size_t)d * HID + lane * 4] = sum;
}

// ------- Hm = softmax((x_emb @ w_hyper + gumbel)*2); M=64, N-split, pipelined, packed ---
__global__ __launch_bounds__(256) void k_hyp(const float* __restrict__ wh_,
                                             const float* __restrict__ u) {
    __shared__ uint32_t As[64 * 20];
    __shared__ uint32_t Bs[8 * 520];
    __shared__ float redM[4][8][2][2];   // [wq][g][AB][wh]
    __shared__ float redS[4][8][2][2];
    int t = threadIdx.x, lane = t & 31, wid = t >> 5;
    int g = lane >> 2, t4 = lane & 3;
    int wq = wid & 3, wh = wid >> 2;
    int r0 = blockIdx.x * 64, m0 = wq * 16;
    float acc[16][4];
#pragma unroll
    for (int n = 0; n < 16; n++) { acc[n][0] = acc[n][1] = acc[n][2] = acc[n][3] = 0.f; }

    bool doA = (t < 128);
    int arow = t >> 1, ak = (t & 1) * 8;               // valid when doA
    int ga = min(r0 + arow, N_NODES - 1);
    int bn = (t & 63) * 4;
    int bpr0 = t >> 6;                                  // l=0 pair-row, l=1 is +4
    int bk0 = (bpr0 >> 2) * 8 + (bpr0 & 3);             // pr 0..3 -> ks0
    int bpr1 = bpr0 + 4;
    int bk1 = (bpr1 >> 2) * 8 + (bpr1 & 3);             // pr 4..7 -> ks1

    float4 fa0, fa1;
    if (doA) {
        fa0 = *(const float4*)(g_xemb + (size_t)ga * HID + ak);
        fa1 = *(const float4*)(g_xemb + (size_t)ga * HID + ak + 4);
    }
    float4 fb00 = *(const float4*)(wh_ + bk0 * HYP + bn);
    float4 fb01 = *(const float4*)(wh_ + (bk0 + 4) * HYP + bn);
    float4 fb10 = *(const float4*)(wh_ + bk1 * HYP + bn);
    float4 fb11 = *(const float4*)(wh_ + (bk1 + 4) * HYP + bn);

    for (int c = 0; c < HID / 16; c++) {
        if (doA) packpair(&As[arow * 20 + ak], fa0, fa1);
        packpair(&Bs[bpr0 * 520 + bn * 2], fb00, fb01);
        packpair(&Bs[bpr1 * 520 + bn * 2], fb10, fb11);
        __syncthreads();
        if (c + 1 < HID / 16) {
            int k0 = (c + 1) * 16;
            if (doA) {
                fa0 = *(const float4*)(g_xemb + (size_t)ga * HID + k0 + ak);
                fa1 = *(const float4*)(g_xemb + (size_t)ga * HID + k0 + ak + 4);
            }
            fb00 = *(const float4*)(wh_ + (k0 + bk0) * HYP + bn);
            fb01 = *(const float4*)(wh_ + (k0 + bk0 + 4) * HYP + bn);
            fb10 = *(const float4*)(wh_ + (k0 + bk1) * HYP + bn);
            fb11 = *(const float4*)(wh_ + (k0 + bk1 + 4) * HYP + bn);
        }
#pragma unroll
        for (int ks = 0; ks < 2; ks++) {
            int ar = (m0 + g) * 20 + ks * 8 + t4 * 2;
            uint2 av0 = *(const uint2*)&As[ar];
            uint2 av1 = *(const uint2*)&As[ar + 160];
            const uint32_t* bp = &Bs[(ks * 4 + t4) * 520 + wh * 256];
#pragma unroll
            for (int nt = 0; nt < 16; nt++) {
                uint2 bv = *(const uint2*)&bp[(nt * 8 + g) * 2];
                mma8(acc[nt], av0.x, av1.x, av0.y, av1.y, bv.x, bv.y);
            }
        }
        __syncthreads();
    }

    int rA = r0 + m0 + g, rB = rA + 8;
    int uA = min(rA, N_NODES - 1), uB = min(rB, N_NODES - 1);
    int cb = wh * 128;
    float mA = -1e30f, mB = -1e30f;
#pragma unroll
    for (int nt = 0; nt < 16; nt++) {
        int cn = cb + nt * 8 + t4 * 2;
        float2 ua = *(const float2*)(u + (size_t)uA * HYP + cn);
        float2 ub = *(const float2*)(u + (size_t)uB * HYP + cn);
        acc[nt][0] = (acc[nt][0] - __logf(-__logf(ua.x + EPSV) + EPSV)) * 2.f;
        acc[nt][1] = (acc[nt][1] - __logf(-__logf(ua.y + EPSV) + EPSV)) * 2.f;
        acc[nt][2] = (acc[nt][2] - __logf(-__logf(ub.x + EPSV) + EPSV)) * 2.f;
        acc[nt][3] = (acc[nt][3] - __logf(-__logf(ub.y + EPSV) + EPSV)) * 2.f;
        mA = fmaxf(mA, fmaxf(acc[nt][0], acc[nt][1]));
        mB = fmaxf(mB, fmaxf(acc[nt][2], acc[nt][3]));
    }
    mA = fmaxf(mA, __shfl_xor_sync(0xffffffffu, mA, 1));
    mA = fmaxf(mA, __shfl_xor_sync(0xffffffffu, mA, 2));
    mB = fmaxf(mB, __shfl_xor_sync(0xffffffffu, mB, 1));
    mB = fmaxf(mB, __shfl_xor_sync(0xffffffffu, mB, 2));
    if (t4 == 0) { redM[wq][g][0][wh] = mA; redM[wq][g][1][wh] = mB; }
    __syncthreads();
    mA = fmaxf(redM[wq][g][0][0], redM[wq][g][0][1]);
    mB = fmaxf(redM[wq][g][1][0], redM[wq][g][1][1]);

    float sA = 0.f, sB = 0.f;
#pragma unroll
    for (int nt = 0; nt < 16; nt++) {
        acc[nt][0] = __expf(acc[nt][0] - mA);
        acc[nt][1] = __expf(acc[nt][1] - mA);
        acc[nt][2] = __expf(acc[nt][2] - mB);
        acc[nt][3] = __expf(acc[nt][3] - mB);
        sA += acc[nt][0] + acc[nt][1];
        sB += acc[nt][2] + acc[nt][3];
    }
    sA += __shfl_xor_sync(0xffffffffu, sA, 1);
    sA += __shfl_xor_sync(0xffffffffu, sA, 2);
    sB += __shfl_xor_sync(0xffffffffu, sB, 1);
    sB += __shfl_xor_sync(0xffffffffu, sB, 2);
    if (t4 == 0) { redS[wq][g][0][wh] = sA; redS[wq][g][1][wh] = sB; }
    __syncthreads();
    float iA = 1.f / (redS[wq][g][0][0] + redS[wq][g][0][1]);
    float iB = 1.f / (redS[wq][g][1][0] + redS[wq][g][1][1]);

#pragma unroll
    for (int nt = 0; nt < 16; nt++) {
        int cn = cb + nt * 8 + t4 * 2;
        if (rA < N_NODES)
            *(float2*)&g_Hm[(size_t)rA * HYP + cn] = make_float2(acc[nt][0] * iA, acc[nt][1] * iA);
        if (rB < N_NODES)
            *(float2*)&g_Hm[(size_t)rB * HYP + cn] = make_float2(acc[nt][2] * iB, acc[nt][3] * iB);
    }
}

// ------- lat partials: latP[b] = Hm[rows_b]^T @ xemb[rows_b] (pipelined, packed) -------
__global__ __launch_bounds__(512) void k_lat() {
    __shared__ uint32_t Hs[8 * 520];   // A pair-packed (m = hyperedge, k = node)
    __shared__ uint32_t Xs[8 * 264];   // B pair-packed
    int t = threadIdx.x, lane = t & 31, wid = t >> 5;
    int g = lane >> 2, t4 = lane & 3;
    int h0 = wid * 16;
    int base = blockIdx.x * NPB;
    float acc[16][4];
#pragma unroll
    for (int n = 0; n < 16; n++) { acc[n][0] = acc[n][1] = acc[n][2] = acc[n][3] = 0.f; }

    int hpr = t >> 6, hn = (t & 63) * 4;               // Hs: all 512 threads
    int hk = (hpr >> 2) * 8 + (hpr & 3);
    bool doX = (t < 256);
    int xpr = t >> 5, xn = (t & 31) * 4;               // Xs: threads 0..255 (xpr 0..7)
    int xk = (xpr >> 2) * 8 + (xpr & 3);

    float4 fh0, fh1, fx0, fx1;
    {
        int n0 = base + hk, n1 = base + hk + 4;
        fh0 = (n0 < N_NODES) ? *(const float4*)&g_Hm[(size_t)n0 * HYP + hn] : make_float4(0,0,0,0);
        fh1 = (n1 < N_NODES) ? *(const float4*)&g_Hm[(size_t)n1 * HYP + hn] : make_float4(0,0,0,0);
        if (doX) {
            int m0n = base + xk, m1n = base + xk + 4;
            fx0 = (m0n < N_NODES) ? *(const float4*)&g_xemb[(size_t)m0n * HID + xn] : make_float4(0,0,0,0);
            fx1 = (m1n < N_NODES) ? *(const float4*)&g_xemb[(size_t)m1n * HID + xn] : make_float4(0,0,0,0);
        }
    }

    for (int c = 0; c < NPB; c += 16) {
        packpair(&Hs[hpr * 520 + hn * 2], fh0, fh1);
        if (doX) packpair(&Xs[xpr * 264 + xn * 2], fx0, fx1);
        __syncthreads();
        if (c + 16 < NPB) {
            int n0 = base + c + 16 + hk, n1 = n0 + 4;
            fh0 = (n0 < N_NODES) ? *(const float4*)&g_Hm[(size_t)n0 * HYP + hn] : make_float4(0,0,0,0);
            fh1 = (n1 < N_NODES) ? *(const float4*)&g_Hm[(size_t)n1 * HYP + hn] : make_float4(0,0,0,0);
            if (doX) {
                int m0n = base + c + 16 + xk, m1n = m0n + 4;
                fx0 = (m0n < N_NODES) ? *(const float4*)&g_xemb[(size_t)m0n * HID + xn] : make_float4(0,0,0,0);
                fx1 = (m1n < N_NODES) ? *(const float4*)&g_xemb[(size_t)m1n * HID + xn] : make_float4(0,0,0,0);
            }
        }
#pragma unroll
        for (int ks = 0; ks < 2; ks++) {
            const uint32_t* hp = &Hs[(ks * 4 + t4) * 520];
            uint2 av0 = *(const uint2*)&hp[(h0 + g) * 2];       // (m, klo),(m, khi)
            uint2 av1 = *(const uint2*)&hp[(h0 + g + 8) * 2];   // (m+8, klo),(m+8, khi)
            const uint32_t* bp = &Xs[(ks * 4 + t4) * 264];
#pragma unroll
            for (int nt = 0; nt < 16; nt++) {
                uint2 bv = *(const uint2*)&bp[(nt * 8 + g) * 2];
                mma8(acc[nt], av0.x, av1.x, av0.y, av1.y, bv.x, bv.y);
            }
        }
        __syncthreads();
    }
    float* pb = &g_latP[(size_t)blockIdx.x * HYP * HID];
#pragma unroll
    for (int nt = 0; nt < 16; nt++) {
        int cn = nt * 8 + t4 * 2;
        *(float2*)&pb[(h0 + g) * HID + cn]     = make_float2(acc[nt][0], acc[nt][1]);
        *(float2*)&pb[(h0 + g + 8) * HID + cn] = make_float2(acc[nt][2], acc[nt][3]);
    }
}

__global__ void k_latred() {
    int i = blockIdx.x * blockDim.x + threadIdx.x;
    if (i < HYP * HID) {
        float s = 0.f;
        for (int b = 0; b < LATB; b++) s += g_latP[(size_t)b * HYP * HID + i];
        g_lat[i] = s;
    }
}

// ------ final = (xemb+c1+c2+c3)/4 + 0.1*normalize(Hm @ lat)  (pipelined, packed) ------
__global__ __launch_bounds__(256) void k_final(float* __restrict__ outF) {
    __shared__ uint32_t As[128 * 20];
    __shared__ uint32_t Bs[8 * 264];
    int t = threadIdx.x, lane = t & 31, wid = t >> 5;
    int g = lane >> 2, t4 = lane & 3;
    int r0 = blockIdx.x * 128, m0 = wid * 16;
    float acc[16][4];
#pragma unroll
    for (int n = 0; n < 16; n++) { acc[n][0] = acc[n][1] = acc[n][2] = acc[n][3] = 0.f; }

    int arow = t >> 1, ak = (t & 1) * 8;
    int ga = min(r0 + arow, N_NODES - 1);
    int bpr = t >> 5, bn = (t & 31) * 4;
    int bk = (bpr >> 2) * 8 + (bpr & 3);

    float4 fa0 = *(const float4*)(g_Hm + (size_t)ga * HYP + ak);
    float4 fa1 = *(const float4*)(g_Hm + (size_t)ga * HYP + ak + 4);
    float4 fb0 = *(const float4*)(g_lat + bk * HID + bn);
    float4 fb1 = *(const float4*)(g_lat + (bk + 4) * HID + bn);

    for (int c = 0; c < HYP / 16; c++) {
        packpair(&As[arow * 20 + ak], fa0, fa1);
        packpair(&Bs[bpr * 264 + bn * 2], fb0, fb1);
        __syncthreads();
        if (c + 1 < HYP / 16) {
            int k0 = (c + 1) * 16;
            fa0 = *(const float4*)(g_Hm + (size_t)ga * HYP + k0 + ak);
            fa1 = *(const float4*)(g_Hm + (size_t)ga * HYP + k0 + ak + 4);
            fb0 = *(const float4*)(g_lat + (k0 + bk) * HID + bn);
            fb1 = *(const float4*)(g_lat + (k0 + bk + 4) * HID + bn);
        }
#pragma unroll
        for (int ks = 0; ks < 2; ks++) {
            int ar = (m0 + g) * 20 + ks * 8 + t4 * 2;
            uint2 av0 = *(const uint2*)&As[ar];
            uint2 av1 = *(const uint2*)&As[ar + 160];
            const uint32_t* bp = &Bs[(ks * 4 + t4) * 264];
#pragma unroll
            for (int nt = 0; nt < 16; nt++) {
                uint2 bv = *(const uint2*)&bp[(nt * 8 + g) * 2];
                mma8(acc[nt], av0.x, av1.x, av0.y, av1.y, bv.x, bv.y);
            }
        }
        __syncthreads();
    }

    float ssA = 0.f, ssB = 0.f;
#pragma unroll
    for (int nt = 0; nt < 16; nt++) {
        ssA += acc[nt][0] * acc[nt][0] + acc[nt][1] * acc[nt][1];
        ssB += acc[nt][2] * acc[nt][2] + acc[nt][3] * acc[nt][3];
    }
    ssA += __shfl_xor_sync(0xffffffffu, ssA, 1);
    ssA += __shfl_xor_sync(0xffffffffu, ssA, 2);
    ssB += __shfl_xor_sync(0xffffffffu, ssB, 1);
    ssB += __shfl_xor_sync(0xffffffffu, ssB, 2);
    float iA = 0.1f / fmaxf(sqrtf(ssA), 1e-12f);
    float iB = 0.1f / fmaxf(sqrtf(ssB), 1e-12f);
    int rA = r0 + m0 + g, rB = rA + 8;
#pragma unroll
    for (int nt = 0; nt < 16; nt++) {
        int cn = nt * 8 + t4 * 2;
        if (rA < N_NODES) {
            size_t o = (size_t)rA * HID + cn;
            float2 e0 = *(const float2*)&g_xemb[o];
            float2 c1 = *(const float2*)&g_curA[o];
            float2 c2 = *(const float2*)&g_curB[o];
            float2 c3 = *(const float2*)&g_curC[o];
            float lx = ((e0.x + c1.x) + c2.x) + c3.x;
            float ly = ((e0.y + c1.y) + c2.y) + c3.y;
            *(float2*)&outF[o] =
                make_float2(lx * 0.25f + acc[nt][0] * iA, ly * 0.25f + acc[nt][1] * iA);
        }
        if (rB < N_NODES) {
            size_t o = (size_t)rB * HID + cn;
            float2 e0 = *(const float2*)&g_xemb[o];
            float2 c1 = *(const float2*)&g_curA[o];
            float2 c2 = *(const float2*)&g_curB[o];
            float2 c3 = *(const float2*)&g_curC[o];
            float lx = ((e0.x + c1.x) + c2.x) + c3.x;
            float ly = ((e0.y + c1.y) + c2.y) + c3.y;
            *(float2*)&outF[o] =
                make_float2(lx * 0.25f + acc[nt][2] * iB, ly * 0.25f + acc[nt][3] * iB);
        }
    }
}

// ---------------- vis/txt = relu(final @ [wv|wt] + [bv|bt])  (packed) ----------------
__global__ __launch_bounds__(256) void k_out(const float* __restrict__ fin,
                                             const float* __restrict__ wv, const float* __restrict__ bv,
                                             const float* __restrict__ wt, const float* __restrict__ bt,
                                             float* __restrict__ vis, float* __restrict__ txt) {
    __shared__ uint32_t As[64 * 20];
    __shared__ uint32_t Bs[8 * 520];
    int t = threadIdx.x, lane = t & 31, wid = t >> 5;
    int g = lane >> 2, t4 = lane & 3;
    int mt = wid & 3, half = wid >> 2;
    int r0 = blockIdx.x * 64, m0 = mt * 16;
    float acc[16][4];
#pragma unroll
    for (int n = 0; n < 16; n++) { acc[n][0] = acc[n][1] = acc[n][2] = acc[n][3] = 0.f; }

    bool doA = (t < 128);
    int arow = t >> 1, ak = (t & 1) * 8;
    int ga = min(r0 + arow, N_NODES - 1);
    int bn = (t & 63) * 4;
    int bpr0 = t >> 6, bpr1 = bpr0 + 4;
    int bk0 = (bpr0 >> 2) * 8 + (bpr0 & 3);
    int bk1 = (bpr1 >> 2) * 8 + (bpr1 & 3);
    const float* wsrc = (bn < 128) ? wv : wt;
    int bnl = (bn < 128) ? bn : (bn - 128);

    for (int k0 = 0; k0 < HID; k0 += 16) {
        if (doA) {
            float4 fa0 = *(const float4*)(fin + (size_t)ga * HID + k0 + ak);
            float4 fa1 = *(const float4*)(fin + (size_t)ga * HID + k0 + ak + 4);
            packpair(&As[arow * 20 + ak], fa0, fa1);
        }
        {
            float4 f0 = *(const float4*)(wsrc + (k0 + bk0) * HID + bnl);
            float4 f1 = *(const float4*)(wsrc + (k0 + bk0 + 4) * HID + bnl);
            packpair(&Bs[bpr0 * 520 + bn * 2], f0, f1);
            f0 = *(const float4*)(wsrc + (k0 + bk1) * HID + bnl);
            f1 = *(const float4*)(wsrc + (k0 + bk1 + 4) * HID + bnl);
            packpair(&Bs[bpr1 * 520 + bn * 2], f0, f1);
        }
        __syncthreads();
#pragma unroll
        for (int ks = 0; ks < 2; ks++) {
            int ar = (m0 + g) * 20 + ks * 8 + t4 * 2;
            uint2 av0 = *(const uint2*)&As[ar];
            uint2 av1 = *(const uint2*)&As[ar + 160];
            const uint32_t* bp = &Bs[(ks * 4 + t4) * 520 + half * 256];
#pragma unroll
            for (int nt = 0; nt < 16; nt++) {
                uint2 bv = *(const uint2*)&bp[(nt * 8 + g) * 2];
                mma8(acc[nt], av0.x, av1.x, av0.y, av1.y, bv.x, bv.y);
            }
        }
        __syncthreads();
    }

    const float* bias = half ? bt : bv;
    float* o = half ? txt : vis;
    int rA = r0 + m0 + g, rB = rA + 8;
#pragma unroll
    for (int nt = 0; nt < 16; nt++) {
        int cn = nt * 8 + t4 * 2;
        float b0 = bias[cn], b1 = bias[cn + 1];
        if (rA < N_NODES)
            *(float2*)&o[(size_t)rA * HID + cn] =
                make_float2(fmaxf(acc[nt][0] + b0, 0.f), fmaxf(acc[nt][1] + b1, 0.f));
        if (rB < N_NODES)
            *(float2*)&o[(size_t)rB * HID + cn] =
                make_float2(fmaxf(acc[nt][2] + b0, 0.f), fmaxf(acc[nt][3] + b1, 0.f));
    }
}

// ---------------- launcher: two-stream fork/join inside graph capture ----------------
extern "C" void kernel_launch(void* const* d_in, const int* in_sizes, int n_in,
                              void* d_out, int out_size) {
    const float* x       = (const float*)d_in[0];
    const int*   ei      = (const int*)  d_in[1];
    const float* u       = (const float*)d_in[2];
    const float* w_feat  = (const float*)d_in[3];
    const float* b_feat  = (const float*)d_in[4];
    const float* w_hyper = (const float*)d_in[5];
    const float* w_vis   = (const float*)d_in[6];
    const float* b_vis   = (const float*)d_in[7];
    const float* w_txt   = (const float*)d_in[8];
    const float* b_txt   = (const float*)d_in[9];

    float* out  = (float*)d_out;
    float* outF = out;
    float* outV = out + (size_t)N_NODES * HID;
    float* outT = out + (size_t)2 * N_NODES * HID;

    const int* src = ei;
    const int* dst = ei + N_EDGES;

    int nb = (N_NODES + 1023) / 1024;         // 49
    int g128 = (N_NODES + 127) / 128;         // 391
    int g64  = (N_NODES + 63) / 64;           // 782

    static cudaStream_t sB = nullptr;
    static cudaEvent_t evFork = nullptr, evFill = nullptr, evG1 = nullptr, evLat = nullptr;
    if (sB == nullptr) {
        cudaStreamCreateWithFlags(&sB, cudaStreamNonBlocking);
        cudaEventCreateWithFlags(&evFork, cudaEventDisableTiming);
        cudaEventCreateWithFlags(&evFill, cudaEventDisableTiming);
        cudaEventCreateWithFlags(&evG1,   cudaEventDisableTiming);
        cudaEventCreateWithFlags(&evLat,  cudaEventDisableTiming);
    }

    cudaEventRecord(evFork, 0);
    cudaStreamWaitEvent(sB, evFork, 0);

    // stream B: CSR setup chain
    k_zero <<<(N_NODES + 255) / 256, 256, 0, sB>>>();
    k_deg  <<<(N_EDGES + 255) / 256, 256, 0, sB>>>(dst);
    k_scan1<<<nb, 1024, 0, sB>>>();
    k_scan2<<<1, 64, 0, sB>>>(nb);
    k_scan3<<<nb, 1024, 0, sB>>>();
    k_fill <<<(N_EDGES + 255) / 256, 256, 0, sB>>>(src, dst);
    cudaEventRecord(evFill, sB);

    // main: feature GEMM (concurrent with setup)
    k_gemm1<<<g128, 256>>>(x, w_feat, b_feat);
    cudaEventRecord(evG1, 0);

    // stream B: hyper branch
    cudaStreamWaitEvent(sB, evG1, 0);
    k_hyp<<<g64, 256, 0, sB>>>(w_hyper, u);
    k_lat<<<LATB, 512, 0, sB>>>();
    k_latred<<<(HYP * HID + 1023) / 1024, 1024, 0, sB>>>();
    cudaEventRecord(evLat, sB);

    // main: propagation
    cudaStreamWaitEvent(0, evFill, 0);
    k_prop<<<(N_NODES + 3) / 4, 128>>>(0);
    k_prop<<<(N_NODES + 3) / 4, 128>>>(1);
    k_prop<<<(N_NODES + 3) / 4, 128>>>(2);

    // join
    cudaStreamWaitEvent(0, evLat, 0);
    k_final<<<g128, 256>>>(outF);
    k_out  <<<g64, 256>>>(outF, w_vis, b_vis, w_txt, b_txt, outV, outT);
}